// round 10
// baseline (speedup 1.0000x reference)
#include <cuda_runtime.h>
#include <cuda_fp16.h>
#include <cstdint>
#include <cstddef>

#define SCALE_Q 0.18033688011112042f  // 0.125 * log2(e)
#define EXP_C 12.0f

__device__ __forceinline__ uint32_t smem_to_u32(const void* p) {
    uint32_t a;
    asm("{ .reg .u64 t; cvta.to.shared.u64 t, %1; cvt.u32.u64 %0, t; }" : "=r"(a) : "l"(p));
    return a;
}
__device__ __forceinline__ void cp16(uint32_t dst, const void* src) {
    asm volatile("cp.async.cg.shared.global [%0], [%1], 16;" :: "r"(dst), "l"(src) : "memory");
}
#define CP_COMMIT() asm volatile("cp.async.commit_group;" ::: "memory")
template <int N>
__device__ __forceinline__ void cp_wait() {
    asm volatile("cp.async.wait_group %0;" :: "n"(N) : "memory");
}
__device__ __forceinline__ void ldm_x4(uint32_t& r0, uint32_t& r1, uint32_t& r2,
                                       uint32_t& r3, uint32_t addr) {
    asm volatile("ldmatrix.sync.aligned.m8n8.x4.shared.b16 {%0,%1,%2,%3}, [%4];"
                 : "=r"(r0), "=r"(r1), "=r"(r2), "=r"(r3) : "r"(addr));
}
__device__ __forceinline__ void ldm_x4t(uint32_t& r0, uint32_t& r1, uint32_t& r2,
                                        uint32_t& r3, uint32_t addr) {
    asm volatile("ldmatrix.sync.aligned.m8n8.x4.trans.shared.b16 {%0,%1,%2,%3}, [%4];"
                 : "=r"(r0), "=r"(r1), "=r"(r2), "=r"(r3) : "r"(addr));
}
__device__ __forceinline__ void mma_f16(float c[4], uint32_t a0, uint32_t a1,
                                        uint32_t a2, uint32_t a3, uint32_t b0,
                                        uint32_t b1) {
    asm volatile(
        "mma.sync.aligned.m16n8k16.row.col.f32.f16.f16.f32 "
        "{%0,%1,%2,%3},{%4,%5,%6,%7},{%8,%9},{%0,%1,%2,%3};\n"
        : "+f"(c[0]), "+f"(c[1]), "+f"(c[2]), "+f"(c[3])
        : "r"(a0), "r"(a1), "r"(a2), "r"(a3), "r"(b0), "r"(b1));
}
__device__ __forceinline__ float ex2f(float x) {
    float r;
    asm("ex2.approx.ftz.f32 %0, %1;" : "=f"(r) : "f"(x));
    return r;
}
__device__ __forceinline__ uint32_t packh2(float lo, float hi) {
    __half2 h = __floats2half2_rn(lo, hi);
    return *(uint32_t*)&h;
}

// ===================== scratch =====================
__device__ __align__(16) __half g_x16[2 * 256 * 4096];     // [b][c][n]
__device__ __align__(16) __half g_w16[768 * 256];          // [o][c]
__device__ __align__(16) __half g_q16[2 * 4 * 4096 * 64];  // [bh][n][d], x 0.125*log2e
__device__ __align__(16) __half g_k16[2 * 4 * 4096 * 64];  // [bh][n][d]
__device__ __align__(16) __half g_v16[2 * 4 * 64 * 4096];  // [bh][dv][m]
__device__ float g_qh[8 * 4096 * 128];                     // [bh][n][r]  (log2 domain)
__device__ float g_qw[8 * 4096 * 128];                     // [bh][n][r]  (log2 domain)

// ---------------------------------------------------------------------------
// Kernel 0: fp32 -> fp16 conversion for x and w
// ---------------------------------------------------------------------------
#define X_F4 524288
#define W_F4 49152
__global__ void __launch_bounds__(256) cvt_kernel(const float* __restrict__ x,
                                                  const float* __restrict__ w) {
    const int idx = blockIdx.x * 256 + threadIdx.x;
    if (idx < X_F4) {
        float4 v = ((const float4*)x)[idx];
        __half2* o = (__half2*)g_x16 + idx * 2;
        o[0] = __floats2half2_rn(v.x, v.y);
        o[1] = __floats2half2_rn(v.z, v.w);
    } else if (idx < X_F4 + W_F4) {
        float4 v = ((const float4*)w)[idx - X_F4];
        __half2* o = (__half2*)g_w16 + (idx - X_F4) * 2;
        o[0] = __floats2half2_rn(v.x, v.y);
        o[1] = __floats2half2_rn(v.z, v.w);
    }
}

// ---------------------------------------------------------------------------
// Kernel 1: QKV projection, fp16 tensor-core GEMM. Q scaled by 0.125*log2e.
// ---------------------------------------------------------------------------
__global__ void __launch_bounds__(256, 1) qkv_mma_kernel() {
    extern __shared__ __align__(128) char smem[];
    const uint32_t sb = smem_to_u32(smem);
    const int t = threadIdx.x;
    const int w = t >> 5, lane = t & 31;
    const int gid = lane >> 2, tig = lane & 3;
    const int wo = w >> 1, wn = w & 1;
    const int n0 = blockIdx.x * 128;
    const int ot = blockIdx.y;
    const int b = blockIdx.z;

    const __half* wg = g_w16 + (size_t)ot * 128 * 256;
    const __half* xg = g_x16 + (size_t)b * 256 * 4096 + n0;

    auto load_stage = [&](int kc, int s) {
        const uint32_t As = sb + s * 32768;
        const uint32_t Bs = As + 16384;
        for (int idx = t; idx < 1024; idx += 256) {
            int row = idx >> 3, ch = idx & 7;
            cp16(As + row * 128 + ((ch ^ (row & 7)) * 16),
                 wg + (size_t)row * 256 + kc * 64 + ch * 8);
        }
        for (int idx = t; idx < 1024; idx += 256) {
            int row = idx >> 4, ch = idx & 15;
            cp16(Bs + row * 256 + ((ch ^ (row & 7)) * 16),
                 xg + (size_t)(kc * 64 + row) * 4096 + ch * 8);
        }
        CP_COMMIT();
    };

    float C[2][8][4];
#pragma unroll
    for (int mt = 0; mt < 2; mt++)
#pragma unroll
        for (int ng = 0; ng < 8; ng++)
#pragma unroll
            for (int e = 0; e < 4; e++) C[mt][ng][e] = 0.f;

    load_stage(0, 0);

    const int a_rlane = ((lane >> 3) & 1) * 8 + (lane & 7);
    const uint32_t a_x = (lane & 7) * 16;
    const int b_row = lane & 15;
    const int b_cg = lane >> 4;

    for (int kc = 0; kc < 4; kc++) {
        if (kc + 1 < 4) {
            load_stage(kc + 1, (kc + 1) & 1);
            cp_wait<1>();
        } else {
            cp_wait<0>();
        }
        __syncthreads();
        const uint32_t As = sb + (kc & 1) * 32768;
        const uint32_t Bs = As + 16384;

#pragma unroll
        for (int ks = 0; ks < 4; ks++) {
            uint32_t af[2][4];
#pragma unroll
            for (int mt = 0; mt < 2; mt++) {
                int arow = wo * 32 + mt * 16 + a_rlane;
                ldm_x4(af[mt][0], af[mt][1], af[mt][2], af[mt][3],
                       As + arow * 128 + (((uint32_t)((ks * 2 + (lane >> 4)) * 16)) ^ a_x));
            }
#pragma unroll
            for (int ng2 = 0; ng2 < 4; ng2++) {
                uint32_t b0, b1, b2, b3;
                int brow = ks * 16 + b_row;
                int bch = wn * 8 + ng2 * 2 + b_cg;
                ldm_x4t(b0, b1, b2, b3,
                        Bs + brow * 256 + ((bch ^ (brow & 7)) * 16));
#pragma unroll
                for (int mt = 0; mt < 2; mt++) {
                    mma_f16(C[mt][2 * ng2], af[mt][0], af[mt][1], af[mt][2], af[mt][3], b0, b1);
                    mma_f16(C[mt][2 * ng2 + 1], af[mt][0], af[mt][1], af[mt][2], af[mt][3], b2, b3);
                }
            }
        }
        __syncthreads();
    }

    const float sc = (ot < 2) ? SCALE_Q : 1.0f;
    __half* Cs = (__half*)smem;
    if (ot < 4) {
#pragma unroll
        for (int mt = 0; mt < 2; mt++) {
            const int r_lo = wo * 32 + mt * 16 + gid, r_hi = r_lo + 8;
#pragma unroll
            for (int ng = 0; ng < 8; ng++) {
                const int c = wn * 64 + ng * 8 + 2 * tig;
                Cs[(c + 0) * 136 + r_lo] = __float2half_rn(C[mt][ng][0] * sc);
                Cs[(c + 1) * 136 + r_lo] = __float2half_rn(C[mt][ng][1] * sc);
                Cs[(c + 0) * 136 + r_hi] = __float2half_rn(C[mt][ng][2] * sc);
                Cs[(c + 1) * 136 + r_hi] = __float2half_rn(C[mt][ng][3] * sc);
            }
        }
        __syncthreads();
        __half* dst = (ot < 2) ? g_q16 : g_k16;
        const int otq = (ot < 2) ? ot : (ot - 2);
        for (int idx = t; idx < 2048; idx += 256) {
            int n = idx >> 4, hs = (idx >> 3) & 1, ch = idx & 7;
            int bh = b * 4 + otq * 2 + hs;
            *(uint4*)(dst + ((size_t)bh * 4096 + n0 + n) * 64 + ch * 8) =
                *(const uint4*)(Cs + n * 136 + hs * 64 + ch * 8);
        }
    } else {
#pragma unroll
        for (int mt = 0; mt < 2; mt++) {
            const int r_lo = wo * 32 + mt * 16 + gid, r_hi = r_lo + 8;
#pragma unroll
            for (int ng = 0; ng < 8; ng++) {
                const int c = wn * 64 + ng * 8 + 2 * tig;
                *(__half2*)(Cs + r_lo * 136 + c) = __floats2half2_rn(C[mt][ng][0], C[mt][ng][1]);
                *(__half2*)(Cs + r_hi * 136 + c) = __floats2half2_rn(C[mt][ng][2], C[mt][ng][3]);
            }
        }
        __syncthreads();
        const int otv = ot - 4;
        for (int idx = t; idx < 2048; idx += 256) {
            int lo = idx >> 4, ch = idx & 15;
            int bh = b * 4 + otv * 2 + (lo >> 6);
            int dv = lo & 63;
            *(uint4*)(g_v16 + ((size_t)bh * 64 + dv) * 4096 + n0 + ch * 8) =
                *(const uint4*)(Cs + lo * 136 + ch * 8);
        }
    }
}

// ---------------------------------------------------------------------------
// Kernel 2: rel-pos logits, fp16 mma (log2-domain outputs).
// ---------------------------------------------------------------------------
__global__ void __launch_bounds__(256) rel_mma_kernel(const float* __restrict__ hrel,
                                                      const float* __restrict__ wrel) {
    __shared__ __align__(128) char smem_r[32768];
    const uint32_t sb = smem_to_u32(smem_r);
    const uint32_t Qs = sb;
    const uint32_t Rs = sb + 16384;
    const int t = threadIdx.x;
    const int w = t >> 5, lane = t & 31;
    const int gid = lane >> 2, tig = lane & 3;
    const int bh = blockIdx.y;
    const int n0 = blockIdx.x * 128;
    const float* rel = blockIdx.z ? wrel : hrel;
    float* outb = blockIdx.z ? g_qw : g_qh;

    for (int idx = t; idx < 1024; idx += 256) {
        int row = idx >> 3, ch = idx & 7;
        cp16(Qs + row * 128 + ((ch ^ (row & 7)) * 16),
             g_q16 + ((size_t)bh * 4096 + n0 + row) * 64 + ch * 8);
    }
    CP_COMMIT();
    for (int idx = t; idx < 1024; idx += 256) {
        int r = idx >> 3, ch = idx & 7;
        __half2 h[4];
        if (r < 127) {
            float4 v0 = *(const float4*)(rel + r * 64 + ch * 8);
            float4 v1 = *(const float4*)(rel + r * 64 + ch * 8 + 4);
            h[0] = __floats2half2_rn(v0.x * 8.f, v0.y * 8.f);
            h[1] = __floats2half2_rn(v0.z * 8.f, v0.w * 8.f);
            h[2] = __floats2half2_rn(v1.x * 8.f, v1.y * 8.f);
            h[3] = __floats2half2_rn(v1.z * 8.f, v1.w * 8.f);
        } else {
            h[0] = h[1] = h[2] = h[3] = __floats2half2_rn(0.f, 0.f);
        }
        *(uint4*)((char*)smem_r + 16384 + r * 128 + ((ch ^ (r & 7)) * 16)) = *(uint4*)h;
    }
    cp_wait<0>();
    __syncthreads();

    const int r0 = w * 16;
    uint32_t qf[4][4];
    {
        const int qrow = r0 + ((lane >> 3) & 1) * 8 + (lane & 7);
        const uint32_t qx = (lane & 7) * 16;
#pragma unroll
        for (int kt = 0; kt < 4; kt++)
            ldm_x4(qf[kt][0], qf[kt][1], qf[kt][2], qf[kt][3],
                   Qs + qrow * 128 + (((uint32_t)((kt * 2 + (lane >> 4)) * 16)) ^ qx));
    }

    const int kv_row = ((lane >> 4) & 1) * 8 + (lane & 7);
    const int kv_csel = (lane >> 3) & 1;
    const uint32_t kv_x = (lane & 7) * 16;

    float S[16][4];
#pragma unroll
    for (int nt = 0; nt < 16; nt++)
#pragma unroll
        for (int e = 0; e < 4; e++) S[nt][e] = 0.f;

#pragma unroll
    for (int kt = 0; kt < 4; kt++) {
#pragma unroll
        for (int ntp = 0; ntp < 8; ntp++) {
            uint32_t b0, b1, b2, b3;
            ldm_x4(b0, b1, b2, b3,
                   Rs + (uint32_t)(ntp * 16 + kv_row) * 128 +
                       (((uint32_t)((kt * 2 + kv_csel) * 16)) ^ kv_x));
            mma_f16(S[2 * ntp], qf[kt][0], qf[kt][1], qf[kt][2], qf[kt][3], b0, b1);
            mma_f16(S[2 * ntp + 1], qf[kt][0], qf[kt][1], qf[kt][2], qf[kt][3], b2, b3);
        }
    }

    const int i_lo = r0 + gid, i_hi = i_lo + 8;
#pragma unroll
    for (int nt = 0; nt < 16; nt++) {
        const int c = nt * 8 + 2 * tig;
        *(float2*)(outb + ((size_t)bh * 4096 + n0 + i_lo) * 128 + c) =
            make_float2(S[nt][0], S[nt][1]);
        *(float2*)(outb + ((size_t)bh * 4096 + n0 + i_hi) * 128 + c) =
            make_float2(S[nt][2], S[nt][3]);
    }
}

// ---------------------------------------------------------------------------
// Kernel 3: fp16 flash attention, 512 threads, key-split warps.
// Warp (wr, wc): query rows [16*wr,+16) x keys [wc*32,+32) of each 64-key tile.
// Max-free softmax is additive -> partial (O, l) summed once at epilogue.
// ---------------------------------------------------------------------------
#define FL_SMEM 68608   // loop: Q16K + K/V 32K; epilogue: Os 33792 + lpart 512 + Opart 33792

__global__ void __launch_bounds__(512, 1) flash_kernel(float* __restrict__ out) {
    extern __shared__ __align__(128) char smem[];
    const uint32_t sb = smem_to_u32(smem);
    const uint32_t Qs = sb;  // 16384
    const uint32_t Kbuf0 = sb + 16384, Kbuf1 = sb + 24576;
    const uint32_t Vbuf0 = sb + 32768, Vbuf1 = sb + 40960;

    const int t = threadIdx.x;
    const int w = t >> 5, lane = t & 31;
    const int gid = lane >> 2, tig = lane & 3;
    const int wr = w >> 1, wc = w & 1;
    const int r0 = wr * 16;
    const int jc = wc * 32;  // key-half offset within 64-key tile
    const int bh = blockIdx.y, qb = blockIdx.x;
    const int n0q = qb * 128;
    const __half* qg = g_q16 + (size_t)bh * 4096 * 64;
    const __half* kg = g_k16 + (size_t)bh * 4096 * 64;
    const __half* vg = g_v16 + (size_t)bh * 64 * 4096;

    for (int c = t; c < 1024; c += 512) {
        int row = c >> 3, kc = c & 7;
        cp16(Qs + row * 128 + ((kc * 16) ^ ((row & 7) * 16)),
             qg + (size_t)(n0q + row) * 64 + kc * 8);
    }
    {
        int row = t >> 3, kc = t & 7;  // t < 512
        uint32_t sw = (kc * 16) ^ ((row & 7) * 16);
        cp16(Kbuf0 + row * 128 + sw, kg + (size_t)row * 64 + kc * 8);
        cp16(Vbuf0 + row * 128 + sw, vg + (size_t)row * 4096 + kc * 8);
    }
    CP_COMMIT();
    cp_wait<0>();
    __syncthreads();

    uint32_t qf[4][4];
    {
        const int qrow = r0 + ((lane >> 3) & 1) * 8 + (lane & 7);
        const uint32_t qx = (lane & 7) * 16;
        const uint32_t qbase = Qs + qrow * 128;
#pragma unroll
        for (int kt = 0; kt < 4; kt++)
            ldm_x4(qf[kt][0], qf[kt][1], qf[kt][2], qf[kt][3],
                   qbase + ((uint32_t)((kt * 2 + (lane >> 4)) * 16) ^ qx));
    }

    const int i_lo = r0 + gid, i_hi = i_lo + 8;
    float qwv[4][4];  // bias for this warp's 32 keys
    {
        const float* qwb = g_qw + ((size_t)bh * 4096 + n0q) * 128;
#pragma unroll
        for (int nt = 0; nt < 4; nt++) {
            int c = jc + nt * 8 + 2 * tig;
            qwv[nt][0] = qwb[(size_t)i_lo * 128 + (c - (i_lo & 63) + 63)];
            qwv[nt][1] = qwb[(size_t)i_lo * 128 + (c + 1 - (i_lo & 63) + 63)];
            qwv[nt][2] = qwb[(size_t)i_hi * 128 + (c - (i_hi & 63) + 63)];
            qwv[nt][3] = qwb[(size_t)i_hi * 128 + (c + 1 - (i_hi & 63) + 63)];
        }
    }
    const float* pqh_lo =
        g_qh + ((size_t)bh * 4096 + n0q + i_lo) * 128 + 63 - (qb * 2 + (i_lo >> 6));
    const float* pqh_hi =
        g_qh + ((size_t)bh * 4096 + n0q + i_hi) * 128 + 63 - (qb * 2 + (i_hi >> 6));

    const int kv_row = ((lane >> 4) & 1) * 8 + (lane & 7);
    const int kv_csel = (lane >> 3) & 1;
    const uint32_t kv_x = (lane & 7) * 16;

    float l_lo = 0.f, l_hi = 0.f;
    float O[8][4];
#pragma unroll
    for (int nt = 0; nt < 8; nt++)
#pragma unroll
        for (int e = 0; e < 4; e++) O[nt][e] = 0.f;

    for (int j = 0; j < 64; j++) {
        __syncthreads();
        if (j + 1 < 64) {
            const uint32_t kb = (j & 1) ? Kbuf0 : Kbuf1;
            const uint32_t vb = (j & 1) ? Vbuf0 : Vbuf1;
            int row = t >> 3, kc = t & 7;
            uint32_t sw = (kc * 16) ^ ((row & 7) * 16);
            cp16(kb + row * 128 + sw, kg + ((size_t)(j + 1) * 64 + row) * 64 + kc * 8);
            cp16(vb + row * 128 + sw, vg + (size_t)row * 4096 + (j + 1) * 64 + kc * 8);
            CP_COMMIT();
            cp_wait<1>();
        } else {
            cp_wait<0>();
        }
        __syncthreads();

        const float qhc_lo = pqh_lo[j] - EXP_C;
        const float qhc_hi = pqh_hi[j] - EXP_C;
        const uint32_t Kb = (j & 1) ? Kbuf1 : Kbuf0;
        const uint32_t Vb = (j & 1) ? Vbuf1 : Vbuf0;

        // ---- S (16 rows x this warp's 32 keys)
        float S[4][4];
#pragma unroll
        for (int nt = 0; nt < 4; nt++)
#pragma unroll
            for (int e = 0; e < 4; e++) S[nt][e] = 0.f;

#pragma unroll
        for (int kt = 0; kt < 4; kt++) {
#pragma unroll
            for (int ntl = 0; ntl < 2; ntl++) {
                uint32_t b0, b1, b2, b3;
                uint32_t addr = Kb + (uint32_t)(jc + ntl * 16 + kv_row) * 128 +
                                ((uint32_t)((kt * 2 + kv_csel) * 16) ^ kv_x);
                ldm_x4(b0, b1, b2, b3, addr);
                mma_f16(S[2 * ntl], qf[kt][0], qf[kt][1], qf[kt][2], qf[kt][3], b0, b1);
                mma_f16(S[2 * ntl + 1], qf[kt][0], qf[kt][1], qf[kt][2], qf[kt][3], b2, b3);
            }
        }

        // ---- max-free softmax
        uint32_t ph[4][2];
        float sum_lo = 0.f, sum_hi = 0.f;
#pragma unroll
        for (int nt = 0; nt < 4; nt++) {
            float e0 = ex2f(S[nt][0] + (qhc_lo + qwv[nt][0]));
            float e1 = ex2f(S[nt][1] + (qhc_lo + qwv[nt][1]));
            float e2 = ex2f(S[nt][2] + (qhc_hi + qwv[nt][2]));
            float e3 = ex2f(S[nt][3] + (qhc_hi + qwv[nt][3]));
            sum_lo += e0 + e1;
            sum_hi += e2 + e3;
            ph[nt][0] = packh2(e0, e1);
            ph[nt][1] = packh2(e2, e3);
        }
        l_lo += sum_lo;
        l_hi += sum_hi;

        // ---- O += P_half @ V_half (k = this warp's 32 keys)
#pragma unroll
        for (int ktl = 0; ktl < 2; ktl++) {
            const uint32_t pa0 = ph[2 * ktl][0], pa1 = ph[2 * ktl][1];
            const uint32_t pa2 = ph[2 * ktl + 1][0], pa3 = ph[2 * ktl + 1][1];
#pragma unroll
            for (int ntp = 0; ntp < 4; ntp++) {
                uint32_t b0, b1, b2, b3;
                uint32_t addr = Vb + (uint32_t)(ntp * 16 + kv_row) * 128 +
                                ((uint32_t)((wc * 4 + ktl * 2 + kv_csel) * 16) ^ kv_x);
                ldm_x4(b0, b1, b2, b3, addr);
                mma_f16(O[2 * ntp], pa0, pa1, pa2, pa3, b0, b1);
                mma_f16(O[2 * ntp + 1], pa0, pa1, pa2, pa3, b2, b3);
            }
        }
    }

    // ---- quad reduction of l (lanes tig 0..3 hold disjoint key columns)
    l_lo += __shfl_xor_sync(0xffffffffu, l_lo, 1);
    l_lo += __shfl_xor_sync(0xffffffffu, l_lo, 2);
    l_hi += __shfl_xor_sync(0xffffffffu, l_hi, 1);
    l_hi += __shfl_xor_sync(0xffffffffu, l_hi, 2);

    __syncthreads();  // all warps done with K/V smem before overwrite

    float* Os = (float*)smem;                    // [dv][i] stride 132 (33792 B)
    float* lpart = (float*)(smem + 33792);       // [128]
    float* Opart = (float*)(smem + 34816);       // [i][dv] stride 66 (33792 B)

    if (wc == 1) {
#pragma unroll
        for (int nt = 0; nt < 8; nt++) {
            int c = nt * 8 + 2 * tig;
            *(float2*)(Opart + i_lo * 66 + c) = make_float2(O[nt][0], O[nt][1]);
            *(float2*)(Opart + i_hi * 66 + c) = make_float2(O[nt][2], O[nt][3]);
        }
        if (tig == 0) {
            lpart[i_lo] = l_lo;
            lpart[i_hi] = l_hi;
        }
    }
    __syncthreads();
    if (wc == 0) {
        const float inv_lo = 1.0f / (l_lo + lpart[i_lo]);
        const float inv_hi = 1.0f / (l_hi + lpart[i_hi]);
#pragma unroll
        for (int nt = 0; nt < 8; nt++) {
            int c = nt * 8 + 2 * tig;
            const float2 p_lo = *(const float2*)(Opart + i_lo * 66 + c);
            const float2 p_hi = *(const float2*)(Opart + i_hi * 66 + c);
            Os[(c + 0) * 132 + i_lo] = (O[nt][0] + p_lo.x) * inv_lo;
            Os[(c + 1) * 132 + i_lo] = (O[nt][1] + p_lo.y) * inv_lo;
            Os[(c + 0) * 132 + i_hi] = (O[nt][2] + p_hi.x) * inv_hi;
            Os[(c + 1) * 132 + i_hi] = (O[nt][3] + p_hi.y) * inv_hi;
        }
    }
    __syncthreads();

    const int b = bh >> 2, head = bh & 3;
    float* outp = out + ((size_t)(b * 256 + head * 64)) * 4096 + n0q;
    for (int idx = t * 4; idx < 8192; idx += 2048) {
        int dv = idx >> 7, i = idx & 127;
        *(float4*)(outp + (size_t)dv * 4096 + i) = *(const float4*)(Os + dv * 132 + i);
    }
}

// ---------------------------------------------------------------------------
extern "C" void kernel_launch(void* const* d_in, const int* in_sizes, int n_in,
                              void* d_out, int out_size) {
    const float* x = (const float*)d_in[0];
    const float* w = (const float*)d_in[1];
    const float* hrel = (const float*)d_in[2];
    const float* wrel = (const float*)d_in[3];
    float* out = (float*)d_out;

    cvt_kernel<<<(X_F4 + W_F4 + 255) / 256, 256>>>(x, w);

    cudaFuncSetAttribute(qkv_mma_kernel, cudaFuncAttributeMaxDynamicSharedMemorySize,
                         65536);
    qkv_mma_kernel<<<dim3(32, 6, 2), 256, 65536>>>();

    rel_mma_kernel<<<dim3(32, 8, 2), 256>>>(hrel, wrel);

    cudaFuncSetAttribute(flash_kernel, cudaFuncAttributeMaxDynamicSharedMemorySize,
                         FL_SMEM);
    flash_kernel<<<dim3(32, 8), 512, FL_SMEM>>>(out);
}

// round 11
// speedup vs baseline: 1.0616x; 1.0616x over previous
#include <cuda_runtime.h>
#include <cuda_fp16.h>
#include <cstdint>
#include <cstddef>

#define SCALE_Q 0.18033688011112042f  // 0.125 * log2(e)
#define EXP_C 12.0f

__device__ __forceinline__ uint32_t smem_to_u32(const void* p) {
    uint32_t a;
    asm("{ .reg .u64 t; cvta.to.shared.u64 t, %1; cvt.u32.u64 %0, t; }" : "=r"(a) : "l"(p));
    return a;
}
__device__ __forceinline__ void cp16(uint32_t dst, const void* src) {
    asm volatile("cp.async.cg.shared.global [%0], [%1], 16;" :: "r"(dst), "l"(src) : "memory");
}
#define CP_COMMIT() asm volatile("cp.async.commit_group;" ::: "memory")
template <int N>
__device__ __forceinline__ void cp_wait() {
    asm volatile("cp.async.wait_group %0;" :: "n"(N) : "memory");
}
__device__ __forceinline__ void ldm_x4(uint32_t& r0, uint32_t& r1, uint32_t& r2,
                                       uint32_t& r3, uint32_t addr) {
    asm volatile("ldmatrix.sync.aligned.m8n8.x4.shared.b16 {%0,%1,%2,%3}, [%4];"
                 : "=r"(r0), "=r"(r1), "=r"(r2), "=r"(r3) : "r"(addr));
}
__device__ __forceinline__ void ldm_x4t(uint32_t& r0, uint32_t& r1, uint32_t& r2,
                                        uint32_t& r3, uint32_t addr) {
    asm volatile("ldmatrix.sync.aligned.m8n8.x4.trans.shared.b16 {%0,%1,%2,%3}, [%4];"
                 : "=r"(r0), "=r"(r1), "=r"(r2), "=r"(r3) : "r"(addr));
}
__device__ __forceinline__ void mma_f16(float c[4], uint32_t a0, uint32_t a1,
                                        uint32_t a2, uint32_t a3, uint32_t b0,
                                        uint32_t b1) {
    asm volatile(
        "mma.sync.aligned.m16n8k16.row.col.f32.f16.f16.f32 "
        "{%0,%1,%2,%3},{%4,%5,%6,%7},{%8,%9},{%0,%1,%2,%3};\n"
        : "+f"(c[0]), "+f"(c[1]), "+f"(c[2]), "+f"(c[3])
        : "r"(a0), "r"(a1), "r"(a2), "r"(a3), "r"(b0), "r"(b1));
}
__device__ __forceinline__ float ex2f(float x) {
    float r;
    asm("ex2.approx.ftz.f32 %0, %1;" : "=f"(r) : "f"(x));
    return r;
}
__device__ __forceinline__ uint32_t packh2(float lo, float hi) {
    __half2 h = __floats2half2_rn(lo, hi);
    return *(uint32_t*)&h;
}

// ===================== scratch =====================
__device__ __align__(16) __half g_x16[2 * 256 * 4096];     // [b][c][n]
__device__ __align__(16) __half g_w16[768 * 256];          // [o][c]
__device__ __align__(16) __half g_q16[2 * 4 * 4096 * 64];  // [bh][n][d], x 0.125*log2e
__device__ __align__(16) __half g_k16[2 * 4 * 4096 * 64];  // [bh][n][d]
__device__ __align__(16) __half g_v16[2 * 4 * 64 * 4096];  // [bh][dv][m]
__device__ float g_qh[8 * 4096 * 128];                     // [bh][n][r]  (log2 domain)
__device__ float g_qw[8 * 4096 * 128];                     // [bh][n][r]  (log2 domain)

// ---------------------------------------------------------------------------
// Kernel 0: fp32 -> fp16 conversion for x and w
// ---------------------------------------------------------------------------
#define X_F4 524288
#define W_F4 49152
__global__ void __launch_bounds__(256) cvt_kernel(const float* __restrict__ x,
                                                  const float* __restrict__ w) {
    const int idx = blockIdx.x * 256 + threadIdx.x;
    if (idx < X_F4) {
        float4 v = ((const float4*)x)[idx];
        __half2* o = (__half2*)g_x16 + idx * 2;
        o[0] = __floats2half2_rn(v.x, v.y);
        o[1] = __floats2half2_rn(v.z, v.w);
    } else if (idx < X_F4 + W_F4) {
        float4 v = ((const float4*)w)[idx - X_F4];
        __half2* o = (__half2*)g_w16 + (idx - X_F4) * 2;
        o[0] = __floats2half2_rn(v.x, v.y);
        o[1] = __floats2half2_rn(v.z, v.w);
    }
}

// ---------------------------------------------------------------------------
// Kernel 1: QKV projection, fp16 tensor-core GEMM. Q scaled by 0.125*log2e.
// ---------------------------------------------------------------------------
__global__ void __launch_bounds__(256, 1) qkv_mma_kernel() {
    extern __shared__ __align__(128) char smem[];
    const uint32_t sb = smem_to_u32(smem);
    const int t = threadIdx.x;
    const int w = t >> 5, lane = t & 31;
    const int gid = lane >> 2, tig = lane & 3;
    const int wo = w >> 1, wn = w & 1;
    const int n0 = blockIdx.x * 128;
    const int ot = blockIdx.y;
    const int b = blockIdx.z;

    const __half* wg = g_w16 + (size_t)ot * 128 * 256;
    const __half* xg = g_x16 + (size_t)b * 256 * 4096 + n0;

    auto load_stage = [&](int kc, int s) {
        const uint32_t As = sb + s * 32768;
        const uint32_t Bs = As + 16384;
        for (int idx = t; idx < 1024; idx += 256) {
            int row = idx >> 3, ch = idx & 7;
            cp16(As + row * 128 + ((ch ^ (row & 7)) * 16),
                 wg + (size_t)row * 256 + kc * 64 + ch * 8);
        }
        for (int idx = t; idx < 1024; idx += 256) {
            int row = idx >> 4, ch = idx & 15;
            cp16(Bs + row * 256 + ((ch ^ (row & 7)) * 16),
                 xg + (size_t)(kc * 64 + row) * 4096 + ch * 8);
        }
        CP_COMMIT();
    };

    float C[2][8][4];
#pragma unroll
    for (int mt = 0; mt < 2; mt++)
#pragma unroll
        for (int ng = 0; ng < 8; ng++)
#pragma unroll
            for (int e = 0; e < 4; e++) C[mt][ng][e] = 0.f;

    load_stage(0, 0);

    const int a_rlane = ((lane >> 3) & 1) * 8 + (lane & 7);
    const uint32_t a_x = (lane & 7) * 16;
    const int b_row = lane & 15;
    const int b_cg = lane >> 4;

    for (int kc = 0; kc < 4; kc++) {
        if (kc + 1 < 4) {
            load_stage(kc + 1, (kc + 1) & 1);
            cp_wait<1>();
        } else {
            cp_wait<0>();
        }
        __syncthreads();
        const uint32_t As = sb + (kc & 1) * 32768;
        const uint32_t Bs = As + 16384;

#pragma unroll
        for (int ks = 0; ks < 4; ks++) {
            uint32_t af[2][4];
#pragma unroll
            for (int mt = 0; mt < 2; mt++) {
                int arow = wo * 32 + mt * 16 + a_rlane;
                ldm_x4(af[mt][0], af[mt][1], af[mt][2], af[mt][3],
                       As + arow * 128 + (((uint32_t)((ks * 2 + (lane >> 4)) * 16)) ^ a_x));
            }
#pragma unroll
            for (int ng2 = 0; ng2 < 4; ng2++) {
                uint32_t b0, b1, b2, b3;
                int brow = ks * 16 + b_row;
                int bch = wn * 8 + ng2 * 2 + b_cg;
                ldm_x4t(b0, b1, b2, b3,
                        Bs + brow * 256 + ((bch ^ (brow & 7)) * 16));
#pragma unroll
                for (int mt = 0; mt < 2; mt++) {
                    mma_f16(C[mt][2 * ng2], af[mt][0], af[mt][1], af[mt][2], af[mt][3], b0, b1);
                    mma_f16(C[mt][2 * ng2 + 1], af[mt][0], af[mt][1], af[mt][2], af[mt][3], b2, b3);
                }
            }
        }
        __syncthreads();
    }

    const float sc = (ot < 2) ? SCALE_Q : 1.0f;
    __half* Cs = (__half*)smem;
    if (ot < 4) {
#pragma unroll
        for (int mt = 0; mt < 2; mt++) {
            const int r_lo = wo * 32 + mt * 16 + gid, r_hi = r_lo + 8;
#pragma unroll
            for (int ng = 0; ng < 8; ng++) {
                const int c = wn * 64 + ng * 8 + 2 * tig;
                Cs[(c + 0) * 136 + r_lo] = __float2half_rn(C[mt][ng][0] * sc);
                Cs[(c + 1) * 136 + r_lo] = __float2half_rn(C[mt][ng][1] * sc);
                Cs[(c + 0) * 136 + r_hi] = __float2half_rn(C[mt][ng][2] * sc);
                Cs[(c + 1) * 136 + r_hi] = __float2half_rn(C[mt][ng][3] * sc);
            }
        }
        __syncthreads();
        __half* dst = (ot < 2) ? g_q16 : g_k16;
        const int otq = (ot < 2) ? ot : (ot - 2);
        for (int idx = t; idx < 2048; idx += 256) {
            int n = idx >> 4, hs = (idx >> 3) & 1, ch = idx & 7;
            int bh = b * 4 + otq * 2 + hs;
            *(uint4*)(dst + ((size_t)bh * 4096 + n0 + n) * 64 + ch * 8) =
                *(const uint4*)(Cs + n * 136 + hs * 64 + ch * 8);
        }
    } else {
#pragma unroll
        for (int mt = 0; mt < 2; mt++) {
            const int r_lo = wo * 32 + mt * 16 + gid, r_hi = r_lo + 8;
#pragma unroll
            for (int ng = 0; ng < 8; ng++) {
                const int c = wn * 64 + ng * 8 + 2 * tig;
                *(__half2*)(Cs + r_lo * 136 + c) = __floats2half2_rn(C[mt][ng][0], C[mt][ng][1]);
                *(__half2*)(Cs + r_hi * 136 + c) = __floats2half2_rn(C[mt][ng][2], C[mt][ng][3]);
            }
        }
        __syncthreads();
        const int otv = ot - 4;
        for (int idx = t; idx < 2048; idx += 256) {
            int lo = idx >> 4, ch = idx & 15;
            int bh = b * 4 + otv * 2 + (lo >> 6);
            int dv = lo & 63;
            *(uint4*)(g_v16 + ((size_t)bh * 64 + dv) * 4096 + n0 + ch * 8) =
                *(const uint4*)(Cs + lo * 136 + ch * 8);
        }
    }
}

// ---------------------------------------------------------------------------
// Kernel 2: rel-pos logits, fp16 mma (log2-domain outputs).
// ---------------------------------------------------------------------------
__global__ void __launch_bounds__(256) rel_mma_kernel(const float* __restrict__ hrel,
                                                      const float* __restrict__ wrel) {
    __shared__ __align__(128) char smem_r[32768];
    const uint32_t sb = smem_to_u32(smem_r);
    const uint32_t Qs = sb;
    const uint32_t Rs = sb + 16384;
    const int t = threadIdx.x;
    const int w = t >> 5, lane = t & 31;
    const int gid = lane >> 2, tig = lane & 3;
    const int bh = blockIdx.y;
    const int n0 = blockIdx.x * 128;
    const float* rel = blockIdx.z ? wrel : hrel;
    float* outb = blockIdx.z ? g_qw : g_qh;

    for (int idx = t; idx < 1024; idx += 256) {
        int row = idx >> 3, ch = idx & 7;
        cp16(Qs + row * 128 + ((ch ^ (row & 7)) * 16),
             g_q16 + ((size_t)bh * 4096 + n0 + row) * 64 + ch * 8);
    }
    CP_COMMIT();
    for (int idx = t; idx < 1024; idx += 256) {
        int r = idx >> 3, ch = idx & 7;
        __half2 h[4];
        if (r < 127) {
            float4 v0 = *(const float4*)(rel + r * 64 + ch * 8);
            float4 v1 = *(const float4*)(rel + r * 64 + ch * 8 + 4);
            h[0] = __floats2half2_rn(v0.x * 8.f, v0.y * 8.f);
            h[1] = __floats2half2_rn(v0.z * 8.f, v0.w * 8.f);
            h[2] = __floats2half2_rn(v1.x * 8.f, v1.y * 8.f);
            h[3] = __floats2half2_rn(v1.z * 8.f, v1.w * 8.f);
        } else {
            h[0] = h[1] = h[2] = h[3] = __floats2half2_rn(0.f, 0.f);
        }
        *(uint4*)((char*)smem_r + 16384 + r * 128 + ((ch ^ (r & 7)) * 16)) = *(uint4*)h;
    }
    cp_wait<0>();
    __syncthreads();

    const int r0 = w * 16;
    uint32_t qf[4][4];
    {
        const int qrow = r0 + ((lane >> 3) & 1) * 8 + (lane & 7);
        const uint32_t qx = (lane & 7) * 16;
#pragma unroll
        for (int kt = 0; kt < 4; kt++)
            ldm_x4(qf[kt][0], qf[kt][1], qf[kt][2], qf[kt][3],
                   Qs + qrow * 128 + (((uint32_t)((kt * 2 + (lane >> 4)) * 16)) ^ qx));
    }

    const int kv_row = ((lane >> 4) & 1) * 8 + (lane & 7);
    const int kv_csel = (lane >> 3) & 1;
    const uint32_t kv_x = (lane & 7) * 16;

    float S[16][4];
#pragma unroll
    for (int nt = 0; nt < 16; nt++)
#pragma unroll
        for (int e = 0; e < 4; e++) S[nt][e] = 0.f;

#pragma unroll
    for (int kt = 0; kt < 4; kt++) {
#pragma unroll
        for (int ntp = 0; ntp < 8; ntp++) {
            uint32_t b0, b1, b2, b3;
            ldm_x4(b0, b1, b2, b3,
                   Rs + (uint32_t)(ntp * 16 + kv_row) * 128 +
                       (((uint32_t)((kt * 2 + kv_csel) * 16)) ^ kv_x));
            mma_f16(S[2 * ntp], qf[kt][0], qf[kt][1], qf[kt][2], qf[kt][3], b0, b1);
            mma_f16(S[2 * ntp + 1], qf[kt][0], qf[kt][1], qf[kt][2], qf[kt][3], b2, b3);
        }
    }

    const int i_lo = r0 + gid, i_hi = i_lo + 8;
#pragma unroll
    for (int nt = 0; nt < 16; nt++) {
        const int c = nt * 8 + 2 * tig;
        *(float2*)(outb + ((size_t)bh * 4096 + n0 + i_lo) * 128 + c) =
            make_float2(S[nt][0], S[nt][1]);
        *(float2*)(outb + ((size_t)bh * 4096 + n0 + i_hi) * 128 + c) =
            make_float2(S[nt][2], S[nt][3]);
    }
}

// ---------------------------------------------------------------------------
// Kernel 3: fp16 flash attention, 512 threads, key-split warps,
// 128 keys per staging round (2 sub-tiles, barrier-free between them).
// ---------------------------------------------------------------------------
#define FL_SMEM 81920   // Q 16K + K 2x16K + V 2x16K

__global__ void __launch_bounds__(512, 1) flash_kernel(float* __restrict__ out) {
    extern __shared__ __align__(128) char smem[];
    const uint32_t sb = smem_to_u32(smem);
    const uint32_t Qs = sb;  // 16384
    const uint32_t Kbuf0 = sb + 16384, Kbuf1 = sb + 32768;   // 16K each (128 keys)
    const uint32_t Vbuf0 = sb + 49152, Vbuf1 = sb + 65536;   // 16K each

    const int t = threadIdx.x;
    const int w = t >> 5, lane = t & 31;
    const int gid = lane >> 2, tig = lane & 3;
    const int wr = w >> 1, wc = w & 1;
    const int r0 = wr * 16;
    const int jc = wc * 32;  // key offset within each 64-key sub-tile
    const int bh = blockIdx.y, qb = blockIdx.x;
    const int n0q = qb * 128;
    const __half* qg = g_q16 + (size_t)bh * 4096 * 64;
    const __half* kg = g_k16 + (size_t)bh * 4096 * 64;
    const __half* vg = g_v16 + (size_t)bh * 64 * 4096;

    // stage round r's 128 keys into (Kb, Vb): 2048 x 16B chunks
    auto stage_round = [&](int r, uint32_t Kb, uint32_t Vb) {
        const int base = r * 128;
#pragma unroll
        for (int pass = 0; pass < 4; pass++) {
            int idx = pass * 512 + t;
            if (idx < 1024) {
                int row = idx >> 3, kc = idx & 7;  // row = key 0..127
                cp16(Kb + row * 128 + ((kc * 16) ^ ((row & 7) * 16)),
                     kg + ((size_t)(base + row)) * 64 + kc * 8);
            } else {
                int vidx = idx - 1024;
                int sub = vidx >> 9;             // 0 or 1
                int dv = (vidx >> 3) & 63;
                int kc = vidx & 7;
                cp16(Vb + sub * 8192 + dv * 128 + ((kc * 16) ^ ((dv & 7) * 16)),
                     vg + (size_t)dv * 4096 + base + sub * 64 + kc * 8);
            }
        }
        CP_COMMIT();
    };

    for (int c = t; c < 1024; c += 512) {
        int row = c >> 3, kc = c & 7;
        cp16(Qs + row * 128 + ((kc * 16) ^ ((row & 7) * 16)),
             qg + (size_t)(n0q + row) * 64 + kc * 8);
    }
    stage_round(0, Kbuf0, Vbuf0);
    cp_wait<0>();
    __syncthreads();

    uint32_t qf[4][4];
    {
        const int qrow = r0 + ((lane >> 3) & 1) * 8 + (lane & 7);
        const uint32_t qx = (lane & 7) * 16;
        const uint32_t qbase = Qs + qrow * 128;
#pragma unroll
        for (int kt = 0; kt < 4; kt++)
            ldm_x4(qf[kt][0], qf[kt][1], qf[kt][2], qf[kt][3],
                   qbase + ((uint32_t)((kt * 2 + (lane >> 4)) * 16) ^ qx));
    }

    const int i_lo = r0 + gid, i_hi = i_lo + 8;
    float qwv[4][4];  // bias for this warp's 32 keys (pattern repeats every 64 keys)
    {
        const float* qwb = g_qw + ((size_t)bh * 4096 + n0q) * 128;
#pragma unroll
        for (int nt = 0; nt < 4; nt++) {
            int c = jc + nt * 8 + 2 * tig;
            qwv[nt][0] = qwb[(size_t)i_lo * 128 + (c - (i_lo & 63) + 63)];
            qwv[nt][1] = qwb[(size_t)i_lo * 128 + (c + 1 - (i_lo & 63) + 63)];
            qwv[nt][2] = qwb[(size_t)i_hi * 128 + (c - (i_hi & 63) + 63)];
            qwv[nt][3] = qwb[(size_t)i_hi * 128 + (c + 1 - (i_hi & 63) + 63)];
        }
    }
    const float* pqh_lo =
        g_qh + ((size_t)bh * 4096 + n0q + i_lo) * 128 + 63 - (qb * 2 + (i_lo >> 6));
    const float* pqh_hi =
        g_qh + ((size_t)bh * 4096 + n0q + i_hi) * 128 + 63 - (qb * 2 + (i_hi >> 6));

    const int kv_row = ((lane >> 4) & 1) * 8 + (lane & 7);
    const int kv_csel = (lane >> 3) & 1;
    const uint32_t kv_x = (lane & 7) * 16;

    float l_lo = 0.f, l_hi = 0.f;
    float O[8][4];
#pragma unroll
    for (int nt = 0; nt < 8; nt++)
#pragma unroll
        for (int e = 0; e < 4; e++) O[nt][e] = 0.f;

    for (int r = 0; r < 32; r++) {
        __syncthreads();
        if (r + 1 < 32) {
            stage_round(r + 1, (r & 1) ? Kbuf0 : Kbuf1, (r & 1) ? Vbuf0 : Vbuf1);
            cp_wait<1>();
        } else {
            cp_wait<0>();
        }
        __syncthreads();

        const uint32_t Kb = (r & 1) ? Kbuf1 : Kbuf0;
        const uint32_t Vb = (r & 1) ? Vbuf1 : Vbuf0;

#pragma unroll
        for (int sub = 0; sub < 2; sub++) {
            const int j = 2 * r + sub;
            const float qhc_lo = pqh_lo[j] - EXP_C;
            const float qhc_hi = pqh_hi[j] - EXP_C;
            const uint32_t Kbs = Kb + sub * 8192;
            const uint32_t Vbs = Vb + sub * 8192;

            // ---- S (16 rows x this warp's 32 keys)
            float S[4][4];
#pragma unroll
            for (int nt = 0; nt < 4; nt++)
#pragma unroll
                for (int e = 0; e < 4; e++) S[nt][e] = 0.f;

#pragma unroll
            for (int kt = 0; kt < 4; kt++) {
#pragma unroll
                for (int ntl = 0; ntl < 2; ntl++) {
                    uint32_t b0, b1, b2, b3;
                    uint32_t addr = Kbs + (uint32_t)(jc + ntl * 16 + kv_row) * 128 +
                                    ((uint32_t)((kt * 2 + kv_csel) * 16) ^ kv_x);
                    ldm_x4(b0, b1, b2, b3, addr);
                    mma_f16(S[2 * ntl], qf[kt][0], qf[kt][1], qf[kt][2], qf[kt][3], b0, b1);
                    mma_f16(S[2 * ntl + 1], qf[kt][0], qf[kt][1], qf[kt][2], qf[kt][3], b2, b3);
                }
            }

            // ---- max-free softmax
            uint32_t ph[4][2];
            float sum_lo = 0.f, sum_hi = 0.f;
#pragma unroll
            for (int nt = 0; nt < 4; nt++) {
                float e0 = ex2f(S[nt][0] + (qhc_lo + qwv[nt][0]));
                float e1 = ex2f(S[nt][1] + (qhc_lo + qwv[nt][1]));
                float e2 = ex2f(S[nt][2] + (qhc_hi + qwv[nt][2]));
                float e3 = ex2f(S[nt][3] + (qhc_hi + qwv[nt][3]));
                sum_lo += e0 + e1;
                sum_hi += e2 + e3;
                ph[nt][0] = packh2(e0, e1);
                ph[nt][1] = packh2(e2, e3);
            }
            l_lo += sum_lo;
            l_hi += sum_hi;

            // ---- O += P_half @ V_half (k = this warp's 32 keys)
#pragma unroll
            for (int ktl = 0; ktl < 2; ktl++) {
                const uint32_t pa0 = ph[2 * ktl][0], pa1 = ph[2 * ktl][1];
                const uint32_t pa2 = ph[2 * ktl + 1][0], pa3 = ph[2 * ktl + 1][1];
#pragma unroll
                for (int ntp = 0; ntp < 4; ntp++) {
                    uint32_t b0, b1, b2, b3;
                    uint32_t addr = Vbs + (uint32_t)(ntp * 16 + kv_row) * 128 +
                                    ((uint32_t)((wc * 4 + ktl * 2 + kv_csel) * 16) ^ kv_x);
                    ldm_x4(b0, b1, b2, b3, addr);
                    mma_f16(O[2 * ntp], pa0, pa1, pa2, pa3, b0, b1);
                    mma_f16(O[2 * ntp + 1], pa0, pa1, pa2, pa3, b2, b3);
                }
            }
        }
    }

    // ---- quad reduction of l
    l_lo += __shfl_xor_sync(0xffffffffu, l_lo, 1);
    l_lo += __shfl_xor_sync(0xffffffffu, l_lo, 2);
    l_hi += __shfl_xor_sync(0xffffffffu, l_hi, 1);
    l_hi += __shfl_xor_sync(0xffffffffu, l_hi, 2);

    __syncthreads();  // all warps done with K/V smem before overwrite

    float* Os = (float*)smem;                    // [dv][i] stride 132 (33792 B)
    float* lpart = (float*)(smem + 33792);       // [128]
    float* Opart = (float*)(smem + 34816);       // [i][dv] stride 66 (33792 B)

    if (wc == 1) {
#pragma unroll
        for (int nt = 0; nt < 8; nt++) {
            int c = nt * 8 + 2 * tig;
            *(float2*)(Opart + i_lo * 66 + c) = make_float2(O[nt][0], O[nt][1]);
            *(float2*)(Opart + i_hi * 66 + c) = make_float2(O[nt][2], O[nt][3]);
        }
        if (tig == 0) {
            lpart[i_lo] = l_lo;
            lpart[i_hi] = l_hi;
        }
    }
    __syncthreads();
    if (wc == 0) {
        const float inv_lo = 1.0f / (l_lo + lpart[i_lo]);
        const float inv_hi = 1.0f / (l_hi + lpart[i_hi]);
#pragma unroll
        for (int nt = 0; nt < 8; nt++) {
            int c = nt * 8 + 2 * tig;
            const float2 p_lo = *(const float2*)(Opart + i_lo * 66 + c);
            const float2 p_hi = *(const float2*)(Opart + i_hi * 66 + c);
            Os[(c + 0) * 132 + i_lo] = (O[nt][0] + p_lo.x) * inv_lo;
            Os[(c + 1) * 132 + i_lo] = (O[nt][1] + p_lo.y) * inv_lo;
            Os[(c + 0) * 132 + i_hi] = (O[nt][2] + p_hi.x) * inv_hi;
            Os[(c + 1) * 132 + i_hi] = (O[nt][3] + p_hi.y) * inv_hi;
        }
    }
    __syncthreads();

    const int b = bh >> 2, head = bh & 3;
    float* outp = out + ((size_t)(b * 256 + head * 64)) * 4096 + n0q;
    for (int idx = t * 4; idx < 8192; idx += 2048) {
        int dv = idx >> 7, i = idx & 127;
        *(float4*)(outp + (size_t)dv * 4096 + i) = *(const float4*)(Os + dv * 132 + i);
    }
}

// ---------------------------------------------------------------------------
extern "C" void kernel_launch(void* const* d_in, const int* in_sizes, int n_in,
                              void* d_out, int out_size) {
    const float* x = (const float*)d_in[0];
    const float* w = (const float*)d_in[1];
    const float* hrel = (const float*)d_in[2];
    const float* wrel = (const float*)d_in[3];
    float* out = (float*)d_out;

    cvt_kernel<<<(X_F4 + W_F4 + 255) / 256, 256>>>(x, w);

    cudaFuncSetAttribute(qkv_mma_kernel, cudaFuncAttributeMaxDynamicSharedMemorySize,
                         65536);
    qkv_mma_kernel<<<dim3(32, 6, 2), 256, 65536>>>();

    rel_mma_kernel<<<dim3(32, 8, 2), 256>>>(hrel, wrel);

    cudaFuncSetAttribute(flash_kernel, cudaFuncAttributeMaxDynamicSharedMemorySize,
                         FL_SMEM);
    flash_kernel<<<dim3(32, 8), 512, FL_SMEM>>>(out);
}

// round 12
// speedup vs baseline: 1.0654x; 1.0036x over previous
#include <cuda_runtime.h>
#include <cuda_fp16.h>
#include <cstdint>
#include <cstddef>

#define SCALE_Q 0.18033688011112042f  // 0.125 * log2(e)
#define EXP_C 12.0f

__device__ __forceinline__ uint32_t smem_to_u32(const void* p) {
    uint32_t a;
    asm("{ .reg .u64 t; cvta.to.shared.u64 t, %1; cvt.u32.u64 %0, t; }" : "=r"(a) : "l"(p));
    return a;
}
__device__ __forceinline__ void cp16(uint32_t dst, const void* src) {
    asm volatile("cp.async.cg.shared.global [%0], [%1], 16;" :: "r"(dst), "l"(src) : "memory");
}
#define CP_COMMIT() asm volatile("cp.async.commit_group;" ::: "memory")
template <int N>
__device__ __forceinline__ void cp_wait() {
    asm volatile("cp.async.wait_group %0;" :: "n"(N) : "memory");
}
__device__ __forceinline__ void ldm_x4(uint32_t& r0, uint32_t& r1, uint32_t& r2,
                                       uint32_t& r3, uint32_t addr) {
    asm volatile("ldmatrix.sync.aligned.m8n8.x4.shared.b16 {%0,%1,%2,%3}, [%4];"
                 : "=r"(r0), "=r"(r1), "=r"(r2), "=r"(r3) : "r"(addr));
}
__device__ __forceinline__ void ldm_x4t(uint32_t& r0, uint32_t& r1, uint32_t& r2,
                                        uint32_t& r3, uint32_t addr) {
    asm volatile("ldmatrix.sync.aligned.m8n8.x4.trans.shared.b16 {%0,%1,%2,%3}, [%4];"
                 : "=r"(r0), "=r"(r1), "=r"(r2), "=r"(r3) : "r"(addr));
}
__device__ __forceinline__ void mma_f16(float c[4], uint32_t a0, uint32_t a1,
                                        uint32_t a2, uint32_t a3, uint32_t b0,
                                        uint32_t b1) {
    asm volatile(
        "mma.sync.aligned.m16n8k16.row.col.f32.f16.f16.f32 "
        "{%0,%1,%2,%3},{%4,%5,%6,%7},{%8,%9},{%0,%1,%2,%3};\n"
        : "+f"(c[0]), "+f"(c[1]), "+f"(c[2]), "+f"(c[3])
        : "r"(a0), "r"(a1), "r"(a2), "r"(a3), "r"(b0), "r"(b1));
}
__device__ __forceinline__ float ex2f(float x) {
    float r;
    asm("ex2.approx.ftz.f32 %0, %1;" : "=f"(r) : "f"(x));
    return r;
}
__device__ __forceinline__ uint32_t packh2(float lo, float hi) {
    __half2 h = __floats2half2_rn(lo, hi);
    return *(uint32_t*)&h;
}

// ===================== scratch =====================
__device__ __align__(16) __half g_x16[2 * 256 * 4096];     // [b][c][n]
__device__ __align__(16) __half g_w16[768 * 256];          // [o][c]
__device__ __align__(16) __half g_q16[2 * 4 * 4096 * 64];  // [bh][n][d], x 0.125*log2e
__device__ __align__(16) __half g_k16[2 * 4 * 4096 * 64];  // [bh][n][d]
__device__ __align__(16) __half g_v16[2 * 4 * 64 * 4096];  // [bh][dv][m]
__device__ float g_qh[8 * 4096 * 128];                     // [bh][n][r]  (log2 domain)
__device__ float g_qw[8 * 4096 * 128];                     // [bh][n][r]  (log2 domain)

// ---------------------------------------------------------------------------
// Kernel 0: fp32 -> fp16 conversion for x and w
// ---------------------------------------------------------------------------
#define X_F4 524288
#define W_F4 49152
__global__ void __launch_bounds__(256) cvt_kernel(const float* __restrict__ x,
                                                  const float* __restrict__ w) {
    const int idx = blockIdx.x * 256 + threadIdx.x;
    if (idx < X_F4) {
        float4 v = ((const float4*)x)[idx];
        __half2* o = (__half2*)g_x16 + idx * 2;
        o[0] = __floats2half2_rn(v.x, v.y);
        o[1] = __floats2half2_rn(v.z, v.w);
    } else if (idx < X_F4 + W_F4) {
        float4 v = ((const float4*)w)[idx - X_F4];
        __half2* o = (__half2*)g_w16 + (idx - X_F4) * 2;
        o[0] = __floats2half2_rn(v.x, v.y);
        o[1] = __floats2half2_rn(v.z, v.w);
    }
}

// ---------------------------------------------------------------------------
// Kernel 1: QKV projection, fp16 tensor-core GEMM. Q scaled by 0.125*log2e.
// ---------------------------------------------------------------------------
__global__ void __launch_bounds__(256, 1) qkv_mma_kernel() {
    extern __shared__ __align__(128) char smem[];
    const uint32_t sb = smem_to_u32(smem);
    const int t = threadIdx.x;
    const int w = t >> 5, lane = t & 31;
    const int gid = lane >> 2, tig = lane & 3;
    const int wo = w >> 1, wn = w & 1;
    const int n0 = blockIdx.x * 128;
    const int ot = blockIdx.y;
    const int b = blockIdx.z;

    const __half* wg = g_w16 + (size_t)ot * 128 * 256;
    const __half* xg = g_x16 + (size_t)b * 256 * 4096 + n0;

    auto load_stage = [&](int kc, int s) {
        const uint32_t As = sb + s * 32768;
        const uint32_t Bs = As + 16384;
        for (int idx = t; idx < 1024; idx += 256) {
            int row = idx >> 3, ch = idx & 7;
            cp16(As + row * 128 + ((ch ^ (row & 7)) * 16),
                 wg + (size_t)row * 256 + kc * 64 + ch * 8);
        }
        for (int idx = t; idx < 1024; idx += 256) {
            int row = idx >> 4, ch = idx & 15;
            cp16(Bs + row * 256 + ((ch ^ (row & 7)) * 16),
                 xg + (size_t)(kc * 64 + row) * 4096 + ch * 8);
        }
        CP_COMMIT();
    };

    float C[2][8][4];
#pragma unroll
    for (int mt = 0; mt < 2; mt++)
#pragma unroll
        for (int ng = 0; ng < 8; ng++)
#pragma unroll
            for (int e = 0; e < 4; e++) C[mt][ng][e] = 0.f;

    load_stage(0, 0);

    const int a_rlane = ((lane >> 3) & 1) * 8 + (lane & 7);
    const uint32_t a_x = (lane & 7) * 16;
    const int b_row = lane & 15;
    const int b_cg = lane >> 4;

    for (int kc = 0; kc < 4; kc++) {
        if (kc + 1 < 4) {
            load_stage(kc + 1, (kc + 1) & 1);
            cp_wait<1>();
        } else {
            cp_wait<0>();
        }
        __syncthreads();
        const uint32_t As = sb + (kc & 1) * 32768;
        const uint32_t Bs = As + 16384;

#pragma unroll
        for (int ks = 0; ks < 4; ks++) {
            uint32_t af[2][4];
#pragma unroll
            for (int mt = 0; mt < 2; mt++) {
                int arow = wo * 32 + mt * 16 + a_rlane;
                ldm_x4(af[mt][0], af[mt][1], af[mt][2], af[mt][3],
                       As + arow * 128 + (((uint32_t)((ks * 2 + (lane >> 4)) * 16)) ^ a_x));
            }
#pragma unroll
            for (int ng2 = 0; ng2 < 4; ng2++) {
                uint32_t b0, b1, b2, b3;
                int brow = ks * 16 + b_row;
                int bch = wn * 8 + ng2 * 2 + b_cg;
                ldm_x4t(b0, b1, b2, b3,
                        Bs + brow * 256 + ((bch ^ (brow & 7)) * 16));
#pragma unroll
                for (int mt = 0; mt < 2; mt++) {
                    mma_f16(C[mt][2 * ng2], af[mt][0], af[mt][1], af[mt][2], af[mt][3], b0, b1);
                    mma_f16(C[mt][2 * ng2 + 1], af[mt][0], af[mt][1], af[mt][2], af[mt][3], b2, b3);
                }
            }
        }
        __syncthreads();
    }

    const float sc = (ot < 2) ? SCALE_Q : 1.0f;
    __half* Cs = (__half*)smem;
    if (ot < 4) {
#pragma unroll
        for (int mt = 0; mt < 2; mt++) {
            const int r_lo = wo * 32 + mt * 16 + gid, r_hi = r_lo + 8;
#pragma unroll
            for (int ng = 0; ng < 8; ng++) {
                const int c = wn * 64 + ng * 8 + 2 * tig;
                Cs[(c + 0) * 136 + r_lo] = __float2half_rn(C[mt][ng][0] * sc);
                Cs[(c + 1) * 136 + r_lo] = __float2half_rn(C[mt][ng][1] * sc);
                Cs[(c + 0) * 136 + r_hi] = __float2half_rn(C[mt][ng][2] * sc);
                Cs[(c + 1) * 136 + r_hi] = __float2half_rn(C[mt][ng][3] * sc);
            }
        }
        __syncthreads();
        __half* dst = (ot < 2) ? g_q16 : g_k16;
        const int otq = (ot < 2) ? ot : (ot - 2);
        for (int idx = t; idx < 2048; idx += 256) {
            int n = idx >> 4, hs = (idx >> 3) & 1, ch = idx & 7;
            int bh = b * 4 + otq * 2 + hs;
            *(uint4*)(dst + ((size_t)bh * 4096 + n0 + n) * 64 + ch * 8) =
                *(const uint4*)(Cs + n * 136 + hs * 64 + ch * 8);
        }
    } else {
#pragma unroll
        for (int mt = 0; mt < 2; mt++) {
            const int r_lo = wo * 32 + mt * 16 + gid, r_hi = r_lo + 8;
#pragma unroll
            for (int ng = 0; ng < 8; ng++) {
                const int c = wn * 64 + ng * 8 + 2 * tig;
                *(__half2*)(Cs + r_lo * 136 + c) = __floats2half2_rn(C[mt][ng][0], C[mt][ng][1]);
                *(__half2*)(Cs + r_hi * 136 + c) = __floats2half2_rn(C[mt][ng][2], C[mt][ng][3]);
            }
        }
        __syncthreads();
        const int otv = ot - 4;
        for (int idx = t; idx < 2048; idx += 256) {
            int lo = idx >> 4, ch = idx & 15;
            int bh = b * 4 + otv * 2 + (lo >> 6);
            int dv = lo & 63;
            *(uint4*)(g_v16 + ((size_t)bh * 64 + dv) * 4096 + n0 + ch * 8) =
                *(const uint4*)(Cs + lo * 136 + ch * 8);
        }
    }
}

// ---------------------------------------------------------------------------
// Kernel 2: rel-pos logits, fp16 mma (log2-domain outputs).
// ---------------------------------------------------------------------------
__global__ void __launch_bounds__(256) rel_mma_kernel(const float* __restrict__ hrel,
                                                      const float* __restrict__ wrel) {
    __shared__ __align__(128) char smem_r[32768];
    const uint32_t sb = smem_to_u32(smem_r);
    const uint32_t Qs = sb;
    const uint32_t Rs = sb + 16384;
    const int t = threadIdx.x;
    const int w = t >> 5, lane = t & 31;
    const int gid = lane >> 2, tig = lane & 3;
    const int bh = blockIdx.y;
    const int n0 = blockIdx.x * 128;
    const float* rel = blockIdx.z ? wrel : hrel;
    float* outb = blockIdx.z ? g_qw : g_qh;

    for (int idx = t; idx < 1024; idx += 256) {
        int row = idx >> 3, ch = idx & 7;
        cp16(Qs + row * 128 + ((ch ^ (row & 7)) * 16),
             g_q16 + ((size_t)bh * 4096 + n0 + row) * 64 + ch * 8);
    }
    CP_COMMIT();
    for (int idx = t; idx < 1024; idx += 256) {
        int r = idx >> 3, ch = idx & 7;
        __half2 h[4];
        if (r < 127) {
            float4 v0 = *(const float4*)(rel + r * 64 + ch * 8);
            float4 v1 = *(const float4*)(rel + r * 64 + ch * 8 + 4);
            h[0] = __floats2half2_rn(v0.x * 8.f, v0.y * 8.f);
            h[1] = __floats2half2_rn(v0.z * 8.f, v0.w * 8.f);
            h[2] = __floats2half2_rn(v1.x * 8.f, v1.y * 8.f);
            h[3] = __floats2half2_rn(v1.z * 8.f, v1.w * 8.f);
        } else {
            h[0] = h[1] = h[2] = h[3] = __floats2half2_rn(0.f, 0.f);
        }
        *(uint4*)((char*)smem_r + 16384 + r * 128 + ((ch ^ (r & 7)) * 16)) = *(uint4*)h;
    }
    cp_wait<0>();
    __syncthreads();

    const int r0 = w * 16;
    uint32_t qf[4][4];
    {
        const int qrow = r0 + ((lane >> 3) & 1) * 8 + (lane & 7);
        const uint32_t qx = (lane & 7) * 16;
#pragma unroll
        for (int kt = 0; kt < 4; kt++)
            ldm_x4(qf[kt][0], qf[kt][1], qf[kt][2], qf[kt][3],
                   Qs + qrow * 128 + (((uint32_t)((kt * 2 + (lane >> 4)) * 16)) ^ qx));
    }

    const int kv_row = ((lane >> 4) & 1) * 8 + (lane & 7);
    const int kv_csel = (lane >> 3) & 1;
    const uint32_t kv_x = (lane & 7) * 16;

    float S[16][4];
#pragma unroll
    for (int nt = 0; nt < 16; nt++)
#pragma unroll
        for (int e = 0; e < 4; e++) S[nt][e] = 0.f;

#pragma unroll
    for (int kt = 0; kt < 4; kt++) {
#pragma unroll
        for (int ntp = 0; ntp < 8; ntp++) {
            uint32_t b0, b1, b2, b3;
            ldm_x4(b0, b1, b2, b3,
                   Rs + (uint32_t)(ntp * 16 + kv_row) * 128 +
                       (((uint32_t)((kt * 2 + kv_csel) * 16)) ^ kv_x));
            mma_f16(S[2 * ntp], qf[kt][0], qf[kt][1], qf[kt][2], qf[kt][3], b0, b1);
            mma_f16(S[2 * ntp + 1], qf[kt][0], qf[kt][1], qf[kt][2], qf[kt][3], b2, b3);
        }
    }

    const int i_lo = r0 + gid, i_hi = i_lo + 8;
#pragma unroll
    for (int nt = 0; nt < 16; nt++) {
        const int c = nt * 8 + 2 * tig;
        *(float2*)(outb + ((size_t)bh * 4096 + n0 + i_lo) * 128 + c) =
            make_float2(S[nt][0], S[nt][1]);
        *(float2*)(outb + ((size_t)bh * 4096 + n0 + i_hi) * 128 + c) =
            make_float2(S[nt][2], S[nt][3]);
    }
}

// ---------------------------------------------------------------------------
// Kernel 3: fp16 flash attention, 256 threads, 8 warps = 4(row) x 2(key).
// Each warp: 32 query rows (2 m-tiles) x 32 keys -> each K/V ldmatrix feeds
// 4 HMMAs (halved LDSM traffic). 128-key staging rounds, max-free softmax.
// ---------------------------------------------------------------------------
#define FL_SMEM 81920   // Q 16K + K 2x16K + V 2x16K

__global__ void __launch_bounds__(256, 1) flash_kernel(float* __restrict__ out) {
    extern __shared__ __align__(128) char smem[];
    const uint32_t sb = smem_to_u32(smem);
    const uint32_t Qs = sb;  // 16384
    const uint32_t Kbuf0 = sb + 16384, Kbuf1 = sb + 32768;   // 16K each (128 keys)
    const uint32_t Vbuf0 = sb + 49152, Vbuf1 = sb + 65536;   // 16K each

    const int t = threadIdx.x;
    const int w = t >> 5, lane = t & 31;
    const int gid = lane >> 2, tig = lane & 3;
    const int wr = w >> 1, wc = w & 1;
    const int r0 = wr * 32;
    const int jc = wc * 32;  // key offset within each 64-key sub-tile
    const int bh = blockIdx.y, qb = blockIdx.x;
    const int n0q = qb * 128;
    const __half* qg = g_q16 + (size_t)bh * 4096 * 64;
    const __half* kg = g_k16 + (size_t)bh * 4096 * 64;
    const __half* vg = g_v16 + (size_t)bh * 64 * 4096;

    // stage round r's 128 keys into (Kb, Vb): 2048 x 16B chunks, 256 threads
    auto stage_round = [&](int r, uint32_t Kb, uint32_t Vb) {
        const int base = r * 128;
#pragma unroll
        for (int pass = 0; pass < 8; pass++) {
            int idx = pass * 256 + t;
            if (idx < 1024) {
                int row = idx >> 3, kc = idx & 7;  // row = key 0..127
                cp16(Kb + row * 128 + ((kc * 16) ^ ((row & 7) * 16)),
                     kg + ((size_t)(base + row)) * 64 + kc * 8);
            } else {
                int vidx = idx - 1024;
                int sub = vidx >> 9;             // 0 or 1
                int dv = (vidx >> 3) & 63;
                int kc = vidx & 7;
                cp16(Vb + sub * 8192 + dv * 128 + ((kc * 16) ^ ((dv & 7) * 16)),
                     vg + (size_t)dv * 4096 + base + sub * 64 + kc * 8);
            }
        }
        CP_COMMIT();
    };

    for (int c = t; c < 1024; c += 256) {
        int row = c >> 3, kc = c & 7;
        cp16(Qs + row * 128 + ((kc * 16) ^ ((row & 7) * 16)),
             qg + (size_t)(n0q + row) * 64 + kc * 8);
    }
    stage_round(0, Kbuf0, Vbuf0);
    cp_wait<0>();
    __syncthreads();

    // Q fragments: 2 m-tiles
    uint32_t qf[2][4][4];
    {
        const uint32_t qx = (lane & 7) * 16;
#pragma unroll
        for (int mt = 0; mt < 2; mt++) {
            const int qrow = r0 + mt * 16 + ((lane >> 3) & 1) * 8 + (lane & 7);
            const uint32_t qbase = Qs + qrow * 128;
#pragma unroll
            for (int kt = 0; kt < 4; kt++)
                ldm_x4(qf[mt][kt][0], qf[mt][kt][1], qf[mt][kt][2], qf[mt][kt][3],
                       qbase + ((uint32_t)((kt * 2 + (lane >> 4)) * 16) ^ qx));
        }
    }

    int i_lo[2], i_hi[2];
#pragma unroll
    for (int mt = 0; mt < 2; mt++) {
        i_lo[mt] = r0 + mt * 16 + gid;
        i_hi[mt] = i_lo[mt] + 8;
    }

    float qwv[2][4][4];  // bias for this warp's 32 keys x 2 m-tiles
    {
        const float* qwb = g_qw + ((size_t)bh * 4096 + n0q) * 128;
#pragma unroll
        for (int mt = 0; mt < 2; mt++)
#pragma unroll
            for (int nt = 0; nt < 4; nt++) {
                int c = jc + nt * 8 + 2 * tig;
                qwv[mt][nt][0] = qwb[(size_t)i_lo[mt] * 128 + (c - (i_lo[mt] & 63) + 63)];
                qwv[mt][nt][1] = qwb[(size_t)i_lo[mt] * 128 + (c + 1 - (i_lo[mt] & 63) + 63)];
                qwv[mt][nt][2] = qwb[(size_t)i_hi[mt] * 128 + (c - (i_hi[mt] & 63) + 63)];
                qwv[mt][nt][3] = qwb[(size_t)i_hi[mt] * 128 + (c + 1 - (i_hi[mt] & 63) + 63)];
            }
    }
    const float* pqh_lo0 =
        g_qh + ((size_t)bh * 4096 + n0q + i_lo[0]) * 128 + 63 - (qb * 2 + (i_lo[0] >> 6));
    const float* pqh_hi0 =
        g_qh + ((size_t)bh * 4096 + n0q + i_hi[0]) * 128 + 63 - (qb * 2 + (i_hi[0] >> 6));
    const float* pqh_lo1 =
        g_qh + ((size_t)bh * 4096 + n0q + i_lo[1]) * 128 + 63 - (qb * 2 + (i_lo[1] >> 6));
    const float* pqh_hi1 =
        g_qh + ((size_t)bh * 4096 + n0q + i_hi[1]) * 128 + 63 - (qb * 2 + (i_hi[1] >> 6));

    const int kv_row = ((lane >> 4) & 1) * 8 + (lane & 7);
    const int kv_csel = (lane >> 3) & 1;
    const uint32_t kv_x = (lane & 7) * 16;

    float l_lo0 = 0.f, l_hi0 = 0.f, l_lo1 = 0.f, l_hi1 = 0.f;
    float O[2][4][4];   // per m-tile: 4 n-groups (32 dv) ... wait need 64 dv
    float O2[2][4][4];  // second half of dv
#pragma unroll
    for (int mt = 0; mt < 2; mt++)
#pragma unroll
        for (int nt = 0; nt < 4; nt++)
#pragma unroll
            for (int e = 0; e < 4; e++) { O[mt][nt][e] = 0.f; O2[mt][nt][e] = 0.f; }

    for (int r = 0; r < 32; r++) {
        __syncthreads();
        if (r + 1 < 32) {
            stage_round(r + 1, (r & 1) ? Kbuf0 : Kbuf1, (r & 1) ? Vbuf0 : Vbuf1);
            cp_wait<1>();
        } else {
            cp_wait<0>();
        }
        __syncthreads();

        const uint32_t Kb = (r & 1) ? Kbuf1 : Kbuf0;
        const uint32_t Vb = (r & 1) ? Vbuf1 : Vbuf0;

#pragma unroll
        for (int sub = 0; sub < 2; sub++) {
            const int j = 2 * r + sub;
            const float qhc_lo0 = pqh_lo0[j] - EXP_C;
            const float qhc_hi0 = pqh_hi0[j] - EXP_C;
            const float qhc_lo1 = pqh_lo1[j] - EXP_C;
            const float qhc_hi1 = pqh_hi1[j] - EXP_C;
            const uint32_t Kbs = Kb + sub * 8192;
            const uint32_t Vbs = Vb + sub * 8192;

            // ---- S (2 m-tiles x this warp's 32 keys)
            float S[2][4][4];
#pragma unroll
            for (int mt = 0; mt < 2; mt++)
#pragma unroll
                for (int nt = 0; nt < 4; nt++)
#pragma unroll
                    for (int e = 0; e < 4; e++) S[mt][nt][e] = 0.f;

#pragma unroll
            for (int kt = 0; kt < 4; kt++) {
#pragma unroll
                for (int ntl = 0; ntl < 2; ntl++) {
                    uint32_t b0, b1, b2, b3;
                    uint32_t addr = Kbs + (uint32_t)(jc + ntl * 16 + kv_row) * 128 +
                                    ((uint32_t)((kt * 2 + kv_csel) * 16) ^ kv_x);
                    ldm_x4(b0, b1, b2, b3, addr);
#pragma unroll
                    for (int mt = 0; mt < 2; mt++) {
                        mma_f16(S[mt][2 * ntl], qf[mt][kt][0], qf[mt][kt][1],
                                qf[mt][kt][2], qf[mt][kt][3], b0, b1);
                        mma_f16(S[mt][2 * ntl + 1], qf[mt][kt][0], qf[mt][kt][1],
                                qf[mt][kt][2], qf[mt][kt][3], b2, b3);
                    }
                }
            }

            // ---- max-free softmax
            uint32_t ph[2][4][2];
            float sl0 = 0.f, sh0 = 0.f, sl1 = 0.f, sh1 = 0.f;
#pragma unroll
            for (int nt = 0; nt < 4; nt++) {
                {
                    float e0 = ex2f(S[0][nt][0] + (qhc_lo0 + qwv[0][nt][0]));
                    float e1 = ex2f(S[0][nt][1] + (qhc_lo0 + qwv[0][nt][1]));
                    float e2 = ex2f(S[0][nt][2] + (qhc_hi0 + qwv[0][nt][2]));
                    float e3 = ex2f(S[0][nt][3] + (qhc_hi0 + qwv[0][nt][3]));
                    sl0 += e0 + e1; sh0 += e2 + e3;
                    ph[0][nt][0] = packh2(e0, e1);
                    ph[0][nt][1] = packh2(e2, e3);
                }
                {
                    float e0 = ex2f(S[1][nt][0] + (qhc_lo1 + qwv[1][nt][0]));
                    float e1 = ex2f(S[1][nt][1] + (qhc_lo1 + qwv[1][nt][1]));
                    float e2 = ex2f(S[1][nt][2] + (qhc_hi1 + qwv[1][nt][2]));
                    float e3 = ex2f(S[1][nt][3] + (qhc_hi1 + qwv[1][nt][3]));
                    sl1 += e0 + e1; sh1 += e2 + e3;
                    ph[1][nt][0] = packh2(e0, e1);
                    ph[1][nt][1] = packh2(e2, e3);
                }
            }
            l_lo0 += sl0; l_hi0 += sh0; l_lo1 += sl1; l_hi1 += sh1;

            // ---- O += P @ V (k = this warp's 32 keys)
#pragma unroll
            for (int ktl = 0; ktl < 2; ktl++) {
#pragma unroll
                for (int ntp = 0; ntp < 4; ntp++) {
                    uint32_t b0, b1, b2, b3;
                    uint32_t addr = Vbs + (uint32_t)(ntp * 16 + kv_row) * 128 +
                                    ((uint32_t)((wc * 4 + ktl * 2 + kv_csel) * 16) ^ kv_x);
                    ldm_x4(b0, b1, b2, b3, addr);
#pragma unroll
                    for (int mt = 0; mt < 2; mt++) {
                        const uint32_t pa0 = ph[mt][2 * ktl][0], pa1 = ph[mt][2 * ktl][1];
                        const uint32_t pa2 = ph[mt][2 * ktl + 1][0], pa3 = ph[mt][2 * ktl + 1][1];
                        float* d0 = (ntp < 2) ? O[mt][2 * ntp] : O2[mt][2 * (ntp - 2)];
                        float* d1 = (ntp < 2) ? O[mt][2 * ntp + 1] : O2[mt][2 * (ntp - 2) + 1];
                        mma_f16(d0, pa0, pa1, pa2, pa3, b0, b1);
                        mma_f16(d1, pa0, pa1, pa2, pa3, b2, b3);
                    }
                }
            }
        }
    }

    // ---- quad reduction of l
    l_lo0 += __shfl_xor_sync(0xffffffffu, l_lo0, 1);
    l_lo0 += __shfl_xor_sync(0xffffffffu, l_lo0, 2);
    l_hi0 += __shfl_xor_sync(0xffffffffu, l_hi0, 1);
    l_hi0 += __shfl_xor_sync(0xffffffffu, l_hi0, 2);
    l_lo1 += __shfl_xor_sync(0xffffffffu, l_lo1, 1);
    l_lo1 += __shfl_xor_sync(0xffffffffu, l_lo1, 2);
    l_hi1 += __shfl_xor_sync(0xffffffffu, l_hi1, 1);
    l_hi1 += __shfl_xor_sync(0xffffffffu, l_hi1, 2);

    __syncthreads();  // all warps done with K/V smem before overwrite

    float* Os = (float*)smem;                    // [dv][i] stride 132 (33792 B)
    float* lpart = (float*)(smem + 33792);       // [128]
    float* Opart = (float*)(smem + 34816);       // [i][dv] stride 66 (33792 B)

    if (wc == 1) {
#pragma unroll
        for (int mt = 0; mt < 2; mt++) {
#pragma unroll
            for (int nt = 0; nt < 4; nt++) {
                int c0 = nt * 8 + 2 * tig;
                int c1 = 32 + nt * 8 + 2 * tig;
                *(float2*)(Opart + i_lo[mt] * 66 + c0) = make_float2(O[mt][nt][0], O[mt][nt][1]);
                *(float2*)(Opart + i_hi[mt] * 66 + c0) = make_float2(O[mt][nt][2], O[mt][nt][3]);
                *(float2*)(Opart + i_lo[mt] * 66 + c1) = make_float2(O2[mt][nt][0], O2[mt][nt][1]);
                *(float2*)(Opart + i_hi[mt] * 66 + c1) = make_float2(O2[mt][nt][2], O2[mt][nt][3]);
            }
        }
        if (tig == 0) {
            lpart[i_lo[0]] = l_lo0; lpart[i_hi[0]] = l_hi0;
            lpart[i_lo[1]] = l_lo1; lpart[i_hi[1]] = l_hi1;
        }
    }
    __syncthreads();
    if (wc == 0) {
        const float inv_lo0 = 1.0f / (l_lo0 + lpart[i_lo[0]]);
        const float inv_hi0 = 1.0f / (l_hi0 + lpart[i_hi[0]]);
        const float inv_lo1 = 1.0f / (l_lo1 + lpart[i_lo[1]]);
        const float inv_hi1 = 1.0f / (l_hi1 + lpart[i_hi[1]]);
#pragma unroll
        for (int mt = 0; mt < 2; mt++) {
            const float inv_lo = mt ? inv_lo1 : inv_lo0;
            const float inv_hi = mt ? inv_hi1 : inv_hi0;
#pragma unroll
            for (int nt = 0; nt < 4; nt++) {
                int c0 = nt * 8 + 2 * tig;
                int c1 = 32 + nt * 8 + 2 * tig;
                float2 p;
                p = *(const float2*)(Opart + i_lo[mt] * 66 + c0);
                Os[(c0 + 0) * 132 + i_lo[mt]] = (O[mt][nt][0] + p.x) * inv_lo;
                Os[(c0 + 1) * 132 + i_lo[mt]] = (O[mt][nt][1] + p.y) * inv_lo;
                p = *(const float2*)(Opart + i_hi[mt] * 66 + c0);
                Os[(c0 + 0) * 132 + i_hi[mt]] = (O[mt][nt][2] + p.x) * inv_hi;
                Os[(c0 + 1) * 132 + i_hi[mt]] = (O[mt][nt][3] + p.y) * inv_hi;
                p = *(const float2*)(Opart + i_lo[mt] * 66 + c1);
                Os[(c1 + 0) * 132 + i_lo[mt]] = (O2[mt][nt][0] + p.x) * inv_lo;
                Os[(c1 + 1) * 132 + i_lo[mt]] = (O2[mt][nt][1] + p.y) * inv_lo;
                p = *(const float2*)(Opart + i_hi[mt] * 66 + c1);
                Os[(c1 + 0) * 132 + i_hi[mt]] = (O2[mt][nt][2] + p.x) * inv_hi;
                Os[(c1 + 1) * 132 + i_hi[mt]] = (O2[mt][nt][3] + p.y) * inv_hi;
            }
        }
    }
    __syncthreads();

    const int b = bh >> 2, head = bh & 3;
    float* outp = out + ((size_t)(b * 256 + head * 64)) * 4096 + n0q;
    for (int idx = t * 4; idx < 8192; idx += 1024) {
        int dv = idx >> 7, i = idx & 127;
        *(float4*)(outp + (size_t)dv * 4096 + i) = *(const float4*)(Os + dv * 132 + i);
    }
}

// ---------------------------------------------------------------------------
extern "C" void kernel_launch(void* const* d_in, const int* in_sizes, int n_in,
                              void* d_out, int out_size) {
    const float* x = (const float*)d_in[0];
    const float* w = (const float*)d_in[1];
    const float* hrel = (const float*)d_in[2];
    const float* wrel = (const float*)d_in[3];
    float* out = (float*)d_out;

    cvt_kernel<<<(X_F4 + W_F4 + 255) / 256, 256>>>(x, w);

    cudaFuncSetAttribute(qkv_mma_kernel, cudaFuncAttributeMaxDynamicSharedMemorySize,
                         65536);
    qkv_mma_kernel<<<dim3(32, 6, 2), 256, 65536>>>();

    rel_mma_kernel<<<dim3(32, 8, 2), 256>>>(hrel, wrel);

    cudaFuncSetAttribute(flash_kernel, cudaFuncAttributeMaxDynamicSharedMemorySize,
                         FL_SMEM);
    flash_kernel<<<dim3(32, 8), 256, FL_SMEM>>>(out);
}

// round 13
// speedup vs baseline: 1.1016x; 1.0339x over previous
#include <cuda_runtime.h>
#include <cuda_fp16.h>
#include <cstdint>
#include <cstddef>

#define SCALE_Q 0.18033688011112042f  // 0.125 * log2(e)
#define EXP_C 12.0f

__device__ __forceinline__ uint32_t smem_to_u32(const void* p) {
    uint32_t a;
    asm("{ .reg .u64 t; cvta.to.shared.u64 t, %1; cvt.u32.u64 %0, t; }" : "=r"(a) : "l"(p));
    return a;
}
__device__ __forceinline__ void cp16(uint32_t dst, const void* src) {
    asm volatile("cp.async.cg.shared.global [%0], [%1], 16;" :: "r"(dst), "l"(src) : "memory");
}
#define CP_COMMIT() asm volatile("cp.async.commit_group;" ::: "memory")
template <int N>
__device__ __forceinline__ void cp_wait() {
    asm volatile("cp.async.wait_group %0;" :: "n"(N) : "memory");
}
__device__ __forceinline__ void ldm_x4(uint32_t& r0, uint32_t& r1, uint32_t& r2,
                                       uint32_t& r3, uint32_t addr) {
    asm volatile("ldmatrix.sync.aligned.m8n8.x4.shared.b16 {%0,%1,%2,%3}, [%4];"
                 : "=r"(r0), "=r"(r1), "=r"(r2), "=r"(r3) : "r"(addr));
}
__device__ __forceinline__ void ldm_x4t(uint32_t& r0, uint32_t& r1, uint32_t& r2,
                                        uint32_t& r3, uint32_t addr) {
    asm volatile("ldmatrix.sync.aligned.m8n8.x4.trans.shared.b16 {%0,%1,%2,%3}, [%4];"
                 : "=r"(r0), "=r"(r1), "=r"(r2), "=r"(r3) : "r"(addr));
}
__device__ __forceinline__ void mma_f16(float c[4], uint32_t a0, uint32_t a1,
                                        uint32_t a2, uint32_t a3, uint32_t b0,
                                        uint32_t b1) {
    asm volatile(
        "mma.sync.aligned.m16n8k16.row.col.f32.f16.f16.f32 "
        "{%0,%1,%2,%3},{%4,%5,%6,%7},{%8,%9},{%0,%1,%2,%3};\n"
        : "+f"(c[0]), "+f"(c[1]), "+f"(c[2]), "+f"(c[3])
        : "r"(a0), "r"(a1), "r"(a2), "r"(a3), "r"(b0), "r"(b1));
}
__device__ __forceinline__ uint32_t packh2(float lo, float hi) {
    __half2 h = __floats2half2_rn(lo, hi);
    return *(uint32_t*)&h;
}
// paired fp16 exp2: one MUFU op for two logits
__device__ __forceinline__ uint32_t h2ex2(uint32_t x) {
    uint32_t r;
    asm("ex2.approx.f16x2 %0, %1;" : "=r"(r) : "r"(x));
    return r;
}
__device__ __forceinline__ uint32_t hadd2u(uint32_t a, uint32_t b) {
    __half2 r = __hadd2(*(__half2*)&a, *(__half2*)&b);
    return *(uint32_t*)&r;
}

// ===================== scratch =====================
__device__ __align__(16) __half g_x16[2 * 256 * 4096];     // [b][c][n]
__device__ __align__(16) __half g_w16[768 * 256];          // [o][c]
__device__ __align__(16) __half g_q16[2 * 4 * 4096 * 64];  // [bh][n][d], x 0.125*log2e
__device__ __align__(16) __half g_k16[2 * 4 * 4096 * 64];  // [bh][n][d]
__device__ __align__(16) __half g_v16[2 * 4 * 64 * 4096];  // [bh][dv][m]
__device__ float g_qh[8 * 4096 * 128];                     // [bh][n][r]  (log2 domain)
__device__ float g_qw[8 * 4096 * 128];                     // [bh][n][r]  (log2 domain)

// ---------------------------------------------------------------------------
// Kernel 0: fp32 -> fp16 conversion for x and w
// ---------------------------------------------------------------------------
#define X_F4 524288
#define W_F4 49152
__global__ void __launch_bounds__(256) cvt_kernel(const float* __restrict__ x,
                                                  const float* __restrict__ w) {
    const int idx = blockIdx.x * 256 + threadIdx.x;
    if (idx < X_F4) {
        float4 v = ((const float4*)x)[idx];
        __half2* o = (__half2*)g_x16 + idx * 2;
        o[0] = __floats2half2_rn(v.x, v.y);
        o[1] = __floats2half2_rn(v.z, v.w);
    } else if (idx < X_F4 + W_F4) {
        float4 v = ((const float4*)w)[idx - X_F4];
        __half2* o = (__half2*)g_w16 + (idx - X_F4) * 2;
        o[0] = __floats2half2_rn(v.x, v.y);
        o[1] = __floats2half2_rn(v.z, v.w);
    }
}

// ---------------------------------------------------------------------------
// Kernel 1: QKV projection, fp16 tensor-core GEMM. Q scaled by 0.125*log2e.
// ---------------------------------------------------------------------------
__global__ void __launch_bounds__(256, 1) qkv_mma_kernel() {
    extern __shared__ __align__(128) char smem[];
    const uint32_t sb = smem_to_u32(smem);
    const int t = threadIdx.x;
    const int w = t >> 5, lane = t & 31;
    const int gid = lane >> 2, tig = lane & 3;
    const int wo = w >> 1, wn = w & 1;
    const int n0 = blockIdx.x * 128;
    const int ot = blockIdx.y;
    const int b = blockIdx.z;

    const __half* wg = g_w16 + (size_t)ot * 128 * 256;
    const __half* xg = g_x16 + (size_t)b * 256 * 4096 + n0;

    auto load_stage = [&](int kc, int s) {
        const uint32_t As = sb + s * 32768;
        const uint32_t Bs = As + 16384;
        for (int idx = t; idx < 1024; idx += 256) {
            int row = idx >> 3, ch = idx & 7;
            cp16(As + row * 128 + ((ch ^ (row & 7)) * 16),
                 wg + (size_t)row * 256 + kc * 64 + ch * 8);
        }
        for (int idx = t; idx < 1024; idx += 256) {
            int row = idx >> 4, ch = idx & 15;
            cp16(Bs + row * 256 + ((ch ^ (row & 7)) * 16),
                 xg + (size_t)(kc * 64 + row) * 4096 + ch * 8);
        }
        CP_COMMIT();
    };

    float C[2][8][4];
#pragma unroll
    for (int mt = 0; mt < 2; mt++)
#pragma unroll
        for (int ng = 0; ng < 8; ng++)
#pragma unroll
            for (int e = 0; e < 4; e++) C[mt][ng][e] = 0.f;

    load_stage(0, 0);

    const int a_rlane = ((lane >> 3) & 1) * 8 + (lane & 7);
    const uint32_t a_x = (lane & 7) * 16;
    const int b_row = lane & 15;
    const int b_cg = lane >> 4;

    for (int kc = 0; kc < 4; kc++) {
        if (kc + 1 < 4) {
            load_stage(kc + 1, (kc + 1) & 1);
            cp_wait<1>();
        } else {
            cp_wait<0>();
        }
        __syncthreads();
        const uint32_t As = sb + (kc & 1) * 32768;
        const uint32_t Bs = As + 16384;

#pragma unroll
        for (int ks = 0; ks < 4; ks++) {
            uint32_t af[2][4];
#pragma unroll
            for (int mt = 0; mt < 2; mt++) {
                int arow = wo * 32 + mt * 16 + a_rlane;
                ldm_x4(af[mt][0], af[mt][1], af[mt][2], af[mt][3],
                       As + arow * 128 + (((uint32_t)((ks * 2 + (lane >> 4)) * 16)) ^ a_x));
            }
#pragma unroll
            for (int ng2 = 0; ng2 < 4; ng2++) {
                uint32_t b0, b1, b2, b3;
                int brow = ks * 16 + b_row;
                int bch = wn * 8 + ng2 * 2 + b_cg;
                ldm_x4t(b0, b1, b2, b3,
                        Bs + brow * 256 + ((bch ^ (brow & 7)) * 16));
#pragma unroll
                for (int mt = 0; mt < 2; mt++) {
                    mma_f16(C[mt][2 * ng2], af[mt][0], af[mt][1], af[mt][2], af[mt][3], b0, b1);
                    mma_f16(C[mt][2 * ng2 + 1], af[mt][0], af[mt][1], af[mt][2], af[mt][3], b2, b3);
                }
            }
        }
        __syncthreads();
    }

    const float sc = (ot < 2) ? SCALE_Q : 1.0f;
    __half* Cs = (__half*)smem;
    if (ot < 4) {
#pragma unroll
        for (int mt = 0; mt < 2; mt++) {
            const int r_lo = wo * 32 + mt * 16 + gid, r_hi = r_lo + 8;
#pragma unroll
            for (int ng = 0; ng < 8; ng++) {
                const int c = wn * 64 + ng * 8 + 2 * tig;
                Cs[(c + 0) * 136 + r_lo] = __float2half_rn(C[mt][ng][0] * sc);
                Cs[(c + 1) * 136 + r_lo] = __float2half_rn(C[mt][ng][1] * sc);
                Cs[(c + 0) * 136 + r_hi] = __float2half_rn(C[mt][ng][2] * sc);
                Cs[(c + 1) * 136 + r_hi] = __float2half_rn(C[mt][ng][3] * sc);
            }
        }
        __syncthreads();
        __half* dst = (ot < 2) ? g_q16 : g_k16;
        const int otq = (ot < 2) ? ot : (ot - 2);
        for (int idx = t; idx < 2048; idx += 256) {
            int n = idx >> 4, hs = (idx >> 3) & 1, ch = idx & 7;
            int bh = b * 4 + otq * 2 + hs;
            *(uint4*)(dst + ((size_t)bh * 4096 + n0 + n) * 64 + ch * 8) =
                *(const uint4*)(Cs + n * 136 + hs * 64 + ch * 8);
        }
    } else {
#pragma unroll
        for (int mt = 0; mt < 2; mt++) {
            const int r_lo = wo * 32 + mt * 16 + gid, r_hi = r_lo + 8;
#pragma unroll
            for (int ng = 0; ng < 8; ng++) {
                const int c = wn * 64 + ng * 8 + 2 * tig;
                *(__half2*)(Cs + r_lo * 136 + c) = __floats2half2_rn(C[mt][ng][0], C[mt][ng][1]);
                *(__half2*)(Cs + r_hi * 136 + c) = __floats2half2_rn(C[mt][ng][2], C[mt][ng][3]);
            }
        }
        __syncthreads();
        const int otv = ot - 4;
        for (int idx = t; idx < 2048; idx += 256) {
            int lo = idx >> 4, ch = idx & 15;
            int bh = b * 4 + otv * 2 + (lo >> 6);
            int dv = lo & 63;
            *(uint4*)(g_v16 + ((size_t)bh * 64 + dv) * 4096 + n0 + ch * 8) =
                *(const uint4*)(Cs + lo * 136 + ch * 8);
        }
    }
}

// ---------------------------------------------------------------------------
// Kernel 2: rel-pos logits, fp16 mma (log2-domain outputs).
// ---------------------------------------------------------------------------
__global__ void __launch_bounds__(256) rel_mma_kernel(const float* __restrict__ hrel,
                                                      const float* __restrict__ wrel) {
    __shared__ __align__(128) char smem_r[32768];
    const uint32_t sb = smem_to_u32(smem_r);
    const uint32_t Qs = sb;
    const uint32_t Rs = sb + 16384;
    const int t = threadIdx.x;
    const int w = t >> 5, lane = t & 31;
    const int gid = lane >> 2, tig = lane & 3;
    const int bh = blockIdx.y;
    const int n0 = blockIdx.x * 128;
    const float* rel = blockIdx.z ? wrel : hrel;
    float* outb = blockIdx.z ? g_qw : g_qh;

    for (int idx = t; idx < 1024; idx += 256) {
        int row = idx >> 3, ch = idx & 7;
        cp16(Qs + row * 128 + ((ch ^ (row & 7)) * 16),
             g_q16 + ((size_t)bh * 4096 + n0 + row) * 64 + ch * 8);
    }
    CP_COMMIT();
    for (int idx = t; idx < 1024; idx += 256) {
        int r = idx >> 3, ch = idx & 7;
        __half2 h[4];
        if (r < 127) {
            float4 v0 = *(const float4*)(rel + r * 64 + ch * 8);
            float4 v1 = *(const float4*)(rel + r * 64 + ch * 8 + 4);
            h[0] = __floats2half2_rn(v0.x * 8.f, v0.y * 8.f);
            h[1] = __floats2half2_rn(v0.z * 8.f, v0.w * 8.f);
            h[2] = __floats2half2_rn(v1.x * 8.f, v1.y * 8.f);
            h[3] = __floats2half2_rn(v1.z * 8.f, v1.w * 8.f);
        } else {
            h[0] = h[1] = h[2] = h[3] = __floats2half2_rn(0.f, 0.f);
        }
        *(uint4*)((char*)smem_r + 16384 + r * 128 + ((ch ^ (r & 7)) * 16)) = *(uint4*)h;
    }
    cp_wait<0>();
    __syncthreads();

    const int r0 = w * 16;
    uint32_t qf[4][4];
    {
        const int qrow = r0 + ((lane >> 3) & 1) * 8 + (lane & 7);
        const uint32_t qx = (lane & 7) * 16;
#pragma unroll
        for (int kt = 0; kt < 4; kt++)
            ldm_x4(qf[kt][0], qf[kt][1], qf[kt][2], qf[kt][3],
                   Qs + qrow * 128 + (((uint32_t)((kt * 2 + (lane >> 4)) * 16)) ^ qx));
    }

    const int kv_row = ((lane >> 4) & 1) * 8 + (lane & 7);
    const int kv_csel = (lane >> 3) & 1;
    const uint32_t kv_x = (lane & 7) * 16;

    float S[16][4];
#pragma unroll
    for (int nt = 0; nt < 16; nt++)
#pragma unroll
        for (int e = 0; e < 4; e++) S[nt][e] = 0.f;

#pragma unroll
    for (int kt = 0; kt < 4; kt++) {
#pragma unroll
        for (int ntp = 0; ntp < 8; ntp++) {
            uint32_t b0, b1, b2, b3;
            ldm_x4(b0, b1, b2, b3,
                   Rs + (uint32_t)(ntp * 16 + kv_row) * 128 +
                       (((uint32_t)((kt * 2 + kv_csel) * 16)) ^ kv_x));
            mma_f16(S[2 * ntp], qf[kt][0], qf[kt][1], qf[kt][2], qf[kt][3], b0, b1);
            mma_f16(S[2 * ntp + 1], qf[kt][0], qf[kt][1], qf[kt][2], qf[kt][3], b2, b3);
        }
    }

    const int i_lo = r0 + gid, i_hi = i_lo + 8;
#pragma unroll
    for (int nt = 0; nt < 16; nt++) {
        const int c = nt * 8 + 2 * tig;
        *(float2*)(outb + ((size_t)bh * 4096 + n0 + i_lo) * 128 + c) =
            make_float2(S[nt][0], S[nt][1]);
        *(float2*)(outb + ((size_t)bh * 4096 + n0 + i_hi) * 128 + c) =
            make_float2(S[nt][2], S[nt][3]);
    }
}

// ---------------------------------------------------------------------------
// Kernel 3: fp16 flash attention, 256 threads, 8 warps = 4(row) x 2(key).
// f16x2 exp (halved MUFU), max-free softmax, 128-key staging rounds.
// ---------------------------------------------------------------------------
#define FL_SMEM 81920   // Q 16K + K 2x16K + V 2x16K

__global__ void __launch_bounds__(256, 1) flash_kernel(float* __restrict__ out) {
    extern __shared__ __align__(128) char smem[];
    const uint32_t sb = smem_to_u32(smem);
    const uint32_t Qs = sb;  // 16384
    const uint32_t Kbuf0 = sb + 16384, Kbuf1 = sb + 32768;   // 16K each (128 keys)
    const uint32_t Vbuf0 = sb + 49152, Vbuf1 = sb + 65536;   // 16K each

    const int t = threadIdx.x;
    const int w = t >> 5, lane = t & 31;
    const int gid = lane >> 2, tig = lane & 3;
    const int wr = w >> 1, wc = w & 1;
    const int r0 = wr * 32;
    const int jc = wc * 32;  // key offset within each 64-key sub-tile
    const int bh = blockIdx.y, qb = blockIdx.x;
    const int n0q = qb * 128;
    const __half* qg = g_q16 + (size_t)bh * 4096 * 64;
    const __half* kg = g_k16 + (size_t)bh * 4096 * 64;
    const __half* vg = g_v16 + (size_t)bh * 64 * 4096;

    auto stage_round = [&](int r, uint32_t Kb, uint32_t Vb) {
        const int base = r * 128;
#pragma unroll
        for (int pass = 0; pass < 8; pass++) {
            int idx = pass * 256 + t;
            if (idx < 1024) {
                int row = idx >> 3, kc = idx & 7;
                cp16(Kb + row * 128 + ((kc * 16) ^ ((row & 7) * 16)),
                     kg + ((size_t)(base + row)) * 64 + kc * 8);
            } else {
                int vidx = idx - 1024;
                int sub = vidx >> 9;
                int dv = (vidx >> 3) & 63;
                int kc = vidx & 7;
                cp16(Vb + sub * 8192 + dv * 128 + ((kc * 16) ^ ((dv & 7) * 16)),
                     vg + (size_t)dv * 4096 + base + sub * 64 + kc * 8);
            }
        }
        CP_COMMIT();
    };

    for (int c = t; c < 1024; c += 256) {
        int row = c >> 3, kc = c & 7;
        cp16(Qs + row * 128 + ((kc * 16) ^ ((row & 7) * 16)),
             qg + (size_t)(n0q + row) * 64 + kc * 8);
    }
    stage_round(0, Kbuf0, Vbuf0);
    cp_wait<0>();
    __syncthreads();

    uint32_t qf[2][4][4];
    {
        const uint32_t qx = (lane & 7) * 16;
#pragma unroll
        for (int mt = 0; mt < 2; mt++) {
            const int qrow = r0 + mt * 16 + ((lane >> 3) & 1) * 8 + (lane & 7);
            const uint32_t qbase = Qs + qrow * 128;
#pragma unroll
            for (int kt = 0; kt < 4; kt++)
                ldm_x4(qf[mt][kt][0], qf[mt][kt][1], qf[mt][kt][2], qf[mt][kt][3],
                       qbase + ((uint32_t)((kt * 2 + (lane >> 4)) * 16) ^ qx));
        }
    }

    int i_lo[2], i_hi[2];
#pragma unroll
    for (int mt = 0; mt < 2; mt++) {
        i_lo[mt] = r0 + mt * 16 + gid;
        i_hi[mt] = i_lo[mt] + 8;
    }

    float qwv[2][4][4];
    {
        const float* qwb = g_qw + ((size_t)bh * 4096 + n0q) * 128;
#pragma unroll
        for (int mt = 0; mt < 2; mt++)
#pragma unroll
            for (int nt = 0; nt < 4; nt++) {
                int c = jc + nt * 8 + 2 * tig;
                qwv[mt][nt][0] = qwb[(size_t)i_lo[mt] * 128 + (c - (i_lo[mt] & 63) + 63)];
                qwv[mt][nt][1] = qwb[(size_t)i_lo[mt] * 128 + (c + 1 - (i_lo[mt] & 63) + 63)];
                qwv[mt][nt][2] = qwb[(size_t)i_hi[mt] * 128 + (c - (i_hi[mt] & 63) + 63)];
                qwv[mt][nt][3] = qwb[(size_t)i_hi[mt] * 128 + (c + 1 - (i_hi[mt] & 63) + 63)];
            }
    }
    const float* pqh_lo0 =
        g_qh + ((size_t)bh * 4096 + n0q + i_lo[0]) * 128 + 63 - (qb * 2 + (i_lo[0] >> 6));
    const float* pqh_hi0 =
        g_qh + ((size_t)bh * 4096 + n0q + i_hi[0]) * 128 + 63 - (qb * 2 + (i_hi[0] >> 6));
    const float* pqh_lo1 =
        g_qh + ((size_t)bh * 4096 + n0q + i_lo[1]) * 128 + 63 - (qb * 2 + (i_lo[1] >> 6));
    const float* pqh_hi1 =
        g_qh + ((size_t)bh * 4096 + n0q + i_hi[1]) * 128 + 63 - (qb * 2 + (i_hi[1] >> 6));

    const int kv_row = ((lane >> 4) & 1) * 8 + (lane & 7);
    const int kv_csel = (lane >> 3) & 1;
    const uint32_t kv_x = (lane & 7) * 16;

    float l_lo0 = 0.f, l_hi0 = 0.f, l_lo1 = 0.f, l_hi1 = 0.f;
    float O[2][4][4];
    float O2[2][4][4];
#pragma unroll
    for (int mt = 0; mt < 2; mt++)
#pragma unroll
        for (int nt = 0; nt < 4; nt++)
#pragma unroll
            for (int e = 0; e < 4; e++) { O[mt][nt][e] = 0.f; O2[mt][nt][e] = 0.f; }

    for (int r = 0; r < 32; r++) {
        __syncthreads();
        if (r + 1 < 32) {
            stage_round(r + 1, (r & 1) ? Kbuf0 : Kbuf1, (r & 1) ? Vbuf0 : Vbuf1);
            cp_wait<1>();
        } else {
            cp_wait<0>();
        }
        __syncthreads();

        const uint32_t Kb = (r & 1) ? Kbuf1 : Kbuf0;
        const uint32_t Vb = (r & 1) ? Vbuf1 : Vbuf0;

#pragma unroll
        for (int sub = 0; sub < 2; sub++) {
            const int j = 2 * r + sub;
            const float qhc_lo0 = pqh_lo0[j] - EXP_C;
            const float qhc_hi0 = pqh_hi0[j] - EXP_C;
            const float qhc_lo1 = pqh_lo1[j] - EXP_C;
            const float qhc_hi1 = pqh_hi1[j] - EXP_C;
            const uint32_t Kbs = Kb + sub * 8192;
            const uint32_t Vbs = Vb + sub * 8192;

            float S[2][4][4];
#pragma unroll
            for (int mt = 0; mt < 2; mt++)
#pragma unroll
                for (int nt = 0; nt < 4; nt++)
#pragma unroll
                    for (int e = 0; e < 4; e++) S[mt][nt][e] = 0.f;

#pragma unroll
            for (int kt = 0; kt < 4; kt++) {
#pragma unroll
                for (int ntl = 0; ntl < 2; ntl++) {
                    uint32_t b0, b1, b2, b3;
                    uint32_t addr = Kbs + (uint32_t)(jc + ntl * 16 + kv_row) * 128 +
                                    ((uint32_t)((kt * 2 + kv_csel) * 16) ^ kv_x);
                    ldm_x4(b0, b1, b2, b3, addr);
#pragma unroll
                    for (int mt = 0; mt < 2; mt++) {
                        mma_f16(S[mt][2 * ntl], qf[mt][kt][0], qf[mt][kt][1],
                                qf[mt][kt][2], qf[mt][kt][3], b0, b1);
                        mma_f16(S[mt][2 * ntl + 1], qf[mt][kt][0], qf[mt][kt][1],
                                qf[mt][kt][2], qf[mt][kt][3], b2, b3);
                    }
                }
            }

            // ---- max-free softmax, paired fp16 exp (bias adds in fp32)
            uint32_t ph[2][4][2];
            uint32_t hl0 = 0, hh0 = 0, hl1 = 0, hh1 = 0;  // half2 partial sums
#pragma unroll
            for (int nt = 0; nt < 4; nt++) {
                {
                    uint32_t p0 = h2ex2(packh2(S[0][nt][0] + (qhc_lo0 + qwv[0][nt][0]),
                                               S[0][nt][1] + (qhc_lo0 + qwv[0][nt][1])));
                    uint32_t p1 = h2ex2(packh2(S[0][nt][2] + (qhc_hi0 + qwv[0][nt][2]),
                                               S[0][nt][3] + (qhc_hi0 + qwv[0][nt][3])));
                    ph[0][nt][0] = p0;
                    ph[0][nt][1] = p1;
                    hl0 = hadd2u(hl0, p0);
                    hh0 = hadd2u(hh0, p1);
                }
                {
                    uint32_t p0 = h2ex2(packh2(S[1][nt][0] + (qhc_lo1 + qwv[1][nt][0]),
                                               S[1][nt][1] + (qhc_lo1 + qwv[1][nt][1])));
                    uint32_t p1 = h2ex2(packh2(S[1][nt][2] + (qhc_hi1 + qwv[1][nt][2]),
                                               S[1][nt][3] + (qhc_hi1 + qwv[1][nt][3])));
                    ph[1][nt][0] = p0;
                    ph[1][nt][1] = p1;
                    hl1 = hadd2u(hl1, p0);
                    hh1 = hadd2u(hh1, p1);
                }
            }
            {
                float2 f;
                f = __half22float2(*(__half2*)&hl0); l_lo0 += f.x + f.y;
                f = __half22float2(*(__half2*)&hh0); l_hi0 += f.x + f.y;
                f = __half22float2(*(__half2*)&hl1); l_lo1 += f.x + f.y;
                f = __half22float2(*(__half2*)&hh1); l_hi1 += f.x + f.y;
            }

            // ---- O += P @ V (k = this warp's 32 keys)
#pragma unroll
            for (int ktl = 0; ktl < 2; ktl++) {
#pragma unroll
                for (int ntp = 0; ntp < 4; ntp++) {
                    uint32_t b0, b1, b2, b3;
                    uint32_t addr = Vbs + (uint32_t)(ntp * 16 + kv_row) * 128 +
                                    ((uint32_t)((wc * 4 + ktl * 2 + kv_csel) * 16) ^ kv_x);
                    ldm_x4(b0, b1, b2, b3, addr);
#pragma unroll
                    for (int mt = 0; mt < 2; mt++) {
                        const uint32_t pa0 = ph[mt][2 * ktl][0], pa1 = ph[mt][2 * ktl][1];
                        const uint32_t pa2 = ph[mt][2 * ktl + 1][0], pa3 = ph[mt][2 * ktl + 1][1];
                        float* d0 = (ntp < 2) ? O[mt][2 * ntp] : O2[mt][2 * (ntp - 2)];
                        float* d1 = (ntp < 2) ? O[mt][2 * ntp + 1] : O2[mt][2 * (ntp - 2) + 1];
                        mma_f16(d0, pa0, pa1, pa2, pa3, b0, b1);
                        mma_f16(d1, pa0, pa1, pa2, pa3, b2, b3);
                    }
                }
            }
        }
    }

    // ---- quad reduction of l
    l_lo0 += __shfl_xor_sync(0xffffffffu, l_lo0, 1);
    l_lo0 += __shfl_xor_sync(0xffffffffu, l_lo0, 2);
    l_hi0 += __shfl_xor_sync(0xffffffffu, l_hi0, 1);
    l_hi0 += __shfl_xor_sync(0xffffffffu, l_hi0, 2);
    l_lo1 += __shfl_xor_sync(0xffffffffu, l_lo1, 1);
    l_lo1 += __shfl_xor_sync(0xffffffffu, l_lo1, 2);
    l_hi1 += __shfl_xor_sync(0xffffffffu, l_hi1, 1);
    l_hi1 += __shfl_xor_sync(0xffffffffu, l_hi1, 2);

    __syncthreads();

    float* Os = (float*)smem;                    // [dv][i] stride 132
    float* lpart = (float*)(smem + 33792);       // [128]
    float* Opart = (float*)(smem + 34816);       // [i][dv] stride 66

    if (wc == 1) {
#pragma unroll
        for (int mt = 0; mt < 2; mt++) {
#pragma unroll
            for (int nt = 0; nt < 4; nt++) {
                int c0 = nt * 8 + 2 * tig;
                int c1 = 32 + nt * 8 + 2 * tig;
                *(float2*)(Opart + i_lo[mt] * 66 + c0) = make_float2(O[mt][nt][0], O[mt][nt][1]);
                *(float2*)(Opart + i_hi[mt] * 66 + c0) = make_float2(O[mt][nt][2], O[mt][nt][3]);
                *(float2*)(Opart + i_lo[mt] * 66 + c1) = make_float2(O2[mt][nt][0], O2[mt][nt][1]);
                *(float2*)(Opart + i_hi[mt] * 66 + c1) = make_float2(O2[mt][nt][2], O2[mt][nt][3]);
            }
        }
        if (tig == 0) {
            lpart[i_lo[0]] = l_lo0; lpart[i_hi[0]] = l_hi0;
            lpart[i_lo[1]] = l_lo1; lpart[i_hi[1]] = l_hi1;
        }
    }
    __syncthreads();
    if (wc == 0) {
        const float inv_lo0 = 1.0f / (l_lo0 + lpart[i_lo[0]]);
        const float inv_hi0 = 1.0f / (l_hi0 + lpart[i_hi[0]]);
        const float inv_lo1 = 1.0f / (l_lo1 + lpart[i_lo[1]]);
        const float inv_hi1 = 1.0f / (l_hi1 + lpart[i_hi[1]]);
#pragma unroll
        for (int mt = 0; mt < 2; mt++) {
            const float inv_lo = mt ? inv_lo1 : inv_lo0;
            const float inv_hi = mt ? inv_hi1 : inv_hi0;
#pragma unroll
            for (int nt = 0; nt < 4; nt++) {
                int c0 = nt * 8 + 2 * tig;
                int c1 = 32 + nt * 8 + 2 * tig;
                float2 p;
                p = *(const float2*)(Opart + i_lo[mt] * 66 + c0);
                Os[(c0 + 0) * 132 + i_lo[mt]] = (O[mt][nt][0] + p.x) * inv_lo;
                Os[(c0 + 1) * 132 + i_lo[mt]] = (O[mt][nt][1] + p.y) * inv_lo;
                p = *(const float2*)(Opart + i_hi[mt] * 66 + c0);
                Os[(c0 + 0) * 132 + i_hi[mt]] = (O[mt][nt][2] + p.x) * inv_hi;
                Os[(c0 + 1) * 132 + i_hi[mt]] = (O[mt][nt][3] + p.y) * inv_hi;
                p = *(const float2*)(Opart + i_lo[mt] * 66 + c1);
                Os[(c1 + 0) * 132 + i_lo[mt]] = (O2[mt][nt][0] + p.x) * inv_lo;
                Os[(c1 + 1) * 132 + i_lo[mt]] = (O2[mt][nt][1] + p.y) * inv_lo;
                p = *(const float2*)(Opart + i_hi[mt] * 66 + c1);
                Os[(c1 + 0) * 132 + i_hi[mt]] = (O2[mt][nt][2] + p.x) * inv_hi;
                Os[(c1 + 1) * 132 + i_hi[mt]] = (O2[mt][nt][3] + p.y) * inv_hi;
            }
        }
    }
    __syncthreads();

    const int b = bh >> 2, head = bh & 3;
    float* outp = out + ((size_t)(b * 256 + head * 64)) * 4096 + n0q;
    for (int idx = t * 4; idx < 8192; idx += 1024) {
        int dv = idx >> 7, i = idx & 127;
        *(float4*)(outp + (size_t)dv * 4096 + i) = *(const float4*)(Os + dv * 132 + i);
    }
}

// ---------------------------------------------------------------------------
extern "C" void kernel_launch(void* const* d_in, const int* in_sizes, int n_in,
                              void* d_out, int out_size) {
    const float* x = (const float*)d_in[0];
    const float* w = (const float*)d_in[1];
    const float* hrel = (const float*)d_in[2];
    const float* wrel = (const float*)d_in[3];
    float* out = (float*)d_out;

    cvt_kernel<<<(X_F4 + W_F4 + 255) / 256, 256>>>(x, w);

    cudaFuncSetAttribute(qkv_mma_kernel, cudaFuncAttributeMaxDynamicSharedMemorySize,
                         65536);
    qkv_mma_kernel<<<dim3(32, 6, 2), 256, 65536>>>();

    rel_mma_kernel<<<dim3(32, 8, 2), 256>>>(hrel, wrel);

    cudaFuncSetAttribute(flash_kernel, cudaFuncAttributeMaxDynamicSharedMemorySize,
                         FL_SMEM);
    flash_kernel<<<dim3(32, 8), 256, FL_SMEM>>>(out);
}

// round 14
// speedup vs baseline: 1.1048x; 1.0029x over previous
#include <cuda_runtime.h>
#include <cuda_fp16.h>
#include <cstdint>
#include <cstddef>

#define SCALE_Q 0.18033688011112042f  // 0.125 * log2(e)
#define EXP_C 12.0f

__device__ __forceinline__ uint32_t smem_to_u32(const void* p) {
    uint32_t a;
    asm("{ .reg .u64 t; cvta.to.shared.u64 t, %1; cvt.u32.u64 %0, t; }" : "=r"(a) : "l"(p));
    return a;
}
__device__ __forceinline__ void cp16(uint32_t dst, const void* src) {
    asm volatile("cp.async.cg.shared.global [%0], [%1], 16;" :: "r"(dst), "l"(src) : "memory");
}
#define CP_COMMIT() asm volatile("cp.async.commit_group;" ::: "memory")
template <int N>
__device__ __forceinline__ void cp_wait() {
    asm volatile("cp.async.wait_group %0;" :: "n"(N) : "memory");
}
__device__ __forceinline__ void ldm_x4(uint32_t& r0, uint32_t& r1, uint32_t& r2,
                                       uint32_t& r3, uint32_t addr) {
    asm volatile("ldmatrix.sync.aligned.m8n8.x4.shared.b16 {%0,%1,%2,%3}, [%4];"
                 : "=r"(r0), "=r"(r1), "=r"(r2), "=r"(r3) : "r"(addr));
}
__device__ __forceinline__ void ldm_x4t(uint32_t& r0, uint32_t& r1, uint32_t& r2,
                                        uint32_t& r3, uint32_t addr) {
    asm volatile("ldmatrix.sync.aligned.m8n8.x4.trans.shared.b16 {%0,%1,%2,%3}, [%4];"
                 : "=r"(r0), "=r"(r1), "=r"(r2), "=r"(r3) : "r"(addr));
}
__device__ __forceinline__ void mma_f16(float c[4], uint32_t a0, uint32_t a1,
                                        uint32_t a2, uint32_t a3, uint32_t b0,
                                        uint32_t b1) {
    asm volatile(
        "mma.sync.aligned.m16n8k16.row.col.f32.f16.f16.f32 "
        "{%0,%1,%2,%3},{%4,%5,%6,%7},{%8,%9},{%0,%1,%2,%3};\n"
        : "+f"(c[0]), "+f"(c[1]), "+f"(c[2]), "+f"(c[3])
        : "r"(a0), "r"(a1), "r"(a2), "r"(a3), "r"(b0), "r"(b1));
}
__device__ __forceinline__ uint32_t packh2(float lo, float hi) {
    __half2 h = __floats2half2_rn(lo, hi);
    return *(uint32_t*)&h;
}
__device__ __forceinline__ uint32_t h2ex2(uint32_t x) {
    uint32_t r;
    asm("ex2.approx.f16x2 %0, %1;" : "=r"(r) : "r"(x));
    return r;
}
__device__ __forceinline__ uint32_t hadd2u(uint32_t a, uint32_t b) {
    __half2 r = __hadd2(*(__half2*)&a, *(__half2*)&b);
    return *(uint32_t*)&r;
}

// ===================== scratch =====================
__device__ __align__(16) __half g_x16[2 * 256 * 4096];     // [b][c][n]
__device__ __align__(16) __half g_w16[768 * 256];          // [o][c]
__device__ __align__(16) __half g_q16[2 * 4 * 4096 * 64];  // [bh][n][d], x 0.125*log2e
__device__ __align__(16) __half g_k16[2 * 4 * 4096 * 64];  // [bh][n][d]
__device__ __align__(16) __half g_v16[2 * 4 * 64 * 4096];  // [bh][dv][m]
__device__ float g_qh[8 * 4096 * 128];                     // [bh][n][r]  (log2 domain)
__device__ float g_qw[8 * 4096 * 128];                     // [bh][n][r]  (log2 domain)

// ---------------------------------------------------------------------------
// Kernel 0: fp32 -> fp16 conversion for x and w
// ---------------------------------------------------------------------------
#define X_F4 524288
#define W_F4 49152
__global__ void __launch_bounds__(256) cvt_kernel(const float* __restrict__ x,
                                                  const float* __restrict__ w) {
    const int idx = blockIdx.x * 256 + threadIdx.x;
    if (idx < X_F4) {
        float4 v = ((const float4*)x)[idx];
        __half2* o = (__half2*)g_x16 + idx * 2;
        o[0] = __floats2half2_rn(v.x, v.y);
        o[1] = __floats2half2_rn(v.z, v.w);
    } else if (idx < X_F4 + W_F4) {
        float4 v = ((const float4*)w)[idx - X_F4];
        __half2* o = (__half2*)g_w16 + (idx - X_F4) * 2;
        o[0] = __floats2half2_rn(v.x, v.y);
        o[1] = __floats2half2_rn(v.z, v.w);
    }
}

// ---------------------------------------------------------------------------
// Kernel 1: QKV projection, fp16 tensor-core GEMM. Q scaled by 0.125*log2e.
// ---------------------------------------------------------------------------
__global__ void __launch_bounds__(256, 1) qkv_mma_kernel() {
    extern __shared__ __align__(128) char smem[];
    const uint32_t sb = smem_to_u32(smem);
    const int t = threadIdx.x;
    const int w = t >> 5, lane = t & 31;
    const int gid = lane >> 2, tig = lane & 3;
    const int wo = w >> 1, wn = w & 1;
    const int n0 = blockIdx.x * 128;
    const int ot = blockIdx.y;
    const int b = blockIdx.z;

    const __half* wg = g_w16 + (size_t)ot * 128 * 256;
    const __half* xg = g_x16 + (size_t)b * 256 * 4096 + n0;

    auto load_stage = [&](int kc, int s) {
        const uint32_t As = sb + s * 32768;
        const uint32_t Bs = As + 16384;
        for (int idx = t; idx < 1024; idx += 256) {
            int row = idx >> 3, ch = idx & 7;
            cp16(As + row * 128 + ((ch ^ (row & 7)) * 16),
                 wg + (size_t)row * 256 + kc * 64 + ch * 8);
        }
        for (int idx = t; idx < 1024; idx += 256) {
            int row = idx >> 4, ch = idx & 15;
            cp16(Bs + row * 256 + ((ch ^ (row & 7)) * 16),
                 xg + (size_t)(kc * 64 + row) * 4096 + ch * 8);
        }
        CP_COMMIT();
    };

    float C[2][8][4];
#pragma unroll
    for (int mt = 0; mt < 2; mt++)
#pragma unroll
        for (int ng = 0; ng < 8; ng++)
#pragma unroll
            for (int e = 0; e < 4; e++) C[mt][ng][e] = 0.f;

    load_stage(0, 0);

    const int a_rlane = ((lane >> 3) & 1) * 8 + (lane & 7);
    const uint32_t a_x = (lane & 7) * 16;
    const int b_row = lane & 15;
    const int b_cg = lane >> 4;

    for (int kc = 0; kc < 4; kc++) {
        if (kc + 1 < 4) {
            load_stage(kc + 1, (kc + 1) & 1);
            cp_wait<1>();
        } else {
            cp_wait<0>();
        }
        __syncthreads();
        const uint32_t As = sb + (kc & 1) * 32768;
        const uint32_t Bs = As + 16384;

#pragma unroll
        for (int ks = 0; ks < 4; ks++) {
            uint32_t af[2][4];
#pragma unroll
            for (int mt = 0; mt < 2; mt++) {
                int arow = wo * 32 + mt * 16 + a_rlane;
                ldm_x4(af[mt][0], af[mt][1], af[mt][2], af[mt][3],
                       As + arow * 128 + (((uint32_t)((ks * 2 + (lane >> 4)) * 16)) ^ a_x));
            }
#pragma unroll
            for (int ng2 = 0; ng2 < 4; ng2++) {
                uint32_t b0, b1, b2, b3;
                int brow = ks * 16 + b_row;
                int bch = wn * 8 + ng2 * 2 + b_cg;
                ldm_x4t(b0, b1, b2, b3,
                        Bs + brow * 256 + ((bch ^ (brow & 7)) * 16));
#pragma unroll
                for (int mt = 0; mt < 2; mt++) {
                    mma_f16(C[mt][2 * ng2], af[mt][0], af[mt][1], af[mt][2], af[mt][3], b0, b1);
                    mma_f16(C[mt][2 * ng2 + 1], af[mt][0], af[mt][1], af[mt][2], af[mt][3], b2, b3);
                }
            }
        }
        __syncthreads();
    }

    const float sc = (ot < 2) ? SCALE_Q : 1.0f;
    __half* Cs = (__half*)smem;
    if (ot < 4) {
#pragma unroll
        for (int mt = 0; mt < 2; mt++) {
            const int r_lo = wo * 32 + mt * 16 + gid, r_hi = r_lo + 8;
#pragma unroll
            for (int ng = 0; ng < 8; ng++) {
                const int c = wn * 64 + ng * 8 + 2 * tig;
                Cs[(c + 0) * 136 + r_lo] = __float2half_rn(C[mt][ng][0] * sc);
                Cs[(c + 1) * 136 + r_lo] = __float2half_rn(C[mt][ng][1] * sc);
                Cs[(c + 0) * 136 + r_hi] = __float2half_rn(C[mt][ng][2] * sc);
                Cs[(c + 1) * 136 + r_hi] = __float2half_rn(C[mt][ng][3] * sc);
            }
        }
        __syncthreads();
        __half* dst = (ot < 2) ? g_q16 : g_k16;
        const int otq = (ot < 2) ? ot : (ot - 2);
        for (int idx = t; idx < 2048; idx += 256) {
            int n = idx >> 4, hs = (idx >> 3) & 1, ch = idx & 7;
            int bh = b * 4 + otq * 2 + hs;
            *(uint4*)(dst + ((size_t)bh * 4096 + n0 + n) * 64 + ch * 8) =
                *(const uint4*)(Cs + n * 136 + hs * 64 + ch * 8);
        }
    } else {
#pragma unroll
        for (int mt = 0; mt < 2; mt++) {
            const int r_lo = wo * 32 + mt * 16 + gid, r_hi = r_lo + 8;
#pragma unroll
            for (int ng = 0; ng < 8; ng++) {
                const int c = wn * 64 + ng * 8 + 2 * tig;
                *(__half2*)(Cs + r_lo * 136 + c) = __floats2half2_rn(C[mt][ng][0], C[mt][ng][1]);
                *(__half2*)(Cs + r_hi * 136 + c) = __floats2half2_rn(C[mt][ng][2], C[mt][ng][3]);
            }
        }
        __syncthreads();
        const int otv = ot - 4;
        for (int idx = t; idx < 2048; idx += 256) {
            int lo = idx >> 4, ch = idx & 15;
            int bh = b * 4 + otv * 2 + (lo >> 6);
            int dv = lo & 63;
            *(uint4*)(g_v16 + ((size_t)bh * 64 + dv) * 4096 + n0 + ch * 8) =
                *(const uint4*)(Cs + lo * 136 + ch * 8);
        }
    }
}

// ---------------------------------------------------------------------------
// Kernel 2: rel-pos logits, fp16 mma (log2-domain outputs).
// ---------------------------------------------------------------------------
__global__ void __launch_bounds__(256) rel_mma_kernel(const float* __restrict__ hrel,
                                                      const float* __restrict__ wrel) {
    __shared__ __align__(128) char smem_r[32768];
    const uint32_t sb = smem_to_u32(smem_r);
    const uint32_t Qs = sb;
    const uint32_t Rs = sb + 16384;
    const int t = threadIdx.x;
    const int w = t >> 5, lane = t & 31;
    const int gid = lane >> 2, tig = lane & 3;
    const int bh = blockIdx.y;
    const int n0 = blockIdx.x * 128;
    const float* rel = blockIdx.z ? wrel : hrel;
    float* outb = blockIdx.z ? g_qw : g_qh;

    for (int idx = t; idx < 1024; idx += 256) {
        int row = idx >> 3, ch = idx & 7;
        cp16(Qs + row * 128 + ((ch ^ (row & 7)) * 16),
             g_q16 + ((size_t)bh * 4096 + n0 + row) * 64 + ch * 8);
    }
    CP_COMMIT();
    for (int idx = t; idx < 1024; idx += 256) {
        int r = idx >> 3, ch = idx & 7;
        __half2 h[4];
        if (r < 127) {
            float4 v0 = *(const float4*)(rel + r * 64 + ch * 8);
            float4 v1 = *(const float4*)(rel + r * 64 + ch * 8 + 4);
            h[0] = __floats2half2_rn(v0.x * 8.f, v0.y * 8.f);
            h[1] = __floats2half2_rn(v0.z * 8.f, v0.w * 8.f);
            h[2] = __floats2half2_rn(v1.x * 8.f, v1.y * 8.f);
            h[3] = __floats2half2_rn(v1.z * 8.f, v1.w * 8.f);
        } else {
            h[0] = h[1] = h[2] = h[3] = __floats2half2_rn(0.f, 0.f);
        }
        *(uint4*)((char*)smem_r + 16384 + r * 128 + ((ch ^ (r & 7)) * 16)) = *(uint4*)h;
    }
    cp_wait<0>();
    __syncthreads();

    const int r0 = w * 16;
    uint32_t qf[4][4];
    {
        const int qrow = r0 + ((lane >> 3) & 1) * 8 + (lane & 7);
        const uint32_t qx = (lane & 7) * 16;
#pragma unroll
        for (int kt = 0; kt < 4; kt++)
            ldm_x4(qf[kt][0], qf[kt][1], qf[kt][2], qf[kt][3],
                   Qs + qrow * 128 + (((uint32_t)((kt * 2 + (lane >> 4)) * 16)) ^ qx));
    }

    const int kv_row = ((lane >> 4) & 1) * 8 + (lane & 7);
    const int kv_csel = (lane >> 3) & 1;
    const uint32_t kv_x = (lane & 7) * 16;

    float S[16][4];
#pragma unroll
    for (int nt = 0; nt < 16; nt++)
#pragma unroll
        for (int e = 0; e < 4; e++) S[nt][e] = 0.f;

#pragma unroll
    for (int kt = 0; kt < 4; kt++) {
#pragma unroll
        for (int ntp = 0; ntp < 8; ntp++) {
            uint32_t b0, b1, b2, b3;
            ldm_x4(b0, b1, b2, b3,
                   Rs + (uint32_t)(ntp * 16 + kv_row) * 128 +
                       (((uint32_t)((kt * 2 + kv_csel) * 16)) ^ kv_x));
            mma_f16(S[2 * ntp], qf[kt][0], qf[kt][1], qf[kt][2], qf[kt][3], b0, b1);
            mma_f16(S[2 * ntp + 1], qf[kt][0], qf[kt][1], qf[kt][2], qf[kt][3], b2, b3);
        }
    }

    const int i_lo = r0 + gid, i_hi = i_lo + 8;
#pragma unroll
    for (int nt = 0; nt < 16; nt++) {
        const int c = nt * 8 + 2 * tig;
        *(float2*)(outb + ((size_t)bh * 4096 + n0 + i_lo) * 128 + c) =
            make_float2(S[nt][0], S[nt][1]);
        *(float2*)(outb + ((size_t)bh * 4096 + n0 + i_hi) * 128 + c) =
            make_float2(S[nt][2], S[nt][3]);
    }
}

// ---------------------------------------------------------------------------
// Kernel 3: fp16 flash attention, 256 threads, 8 warps = 4(row) x 2(key).
// Software-pipelined: next sub-tile's S-mmas issued before current exp/O
// (tensor/MUFU overlap). 256-key rounds (4 sub-tiles), qwv in smem slab.
// ---------------------------------------------------------------------------
#define QW_OFF 147456
#define FL_SMEM 180224  // Q 16K + K 2x32K + V 2x32K + qw 32K

__global__ void __launch_bounds__(256, 1) flash_kernel(float* __restrict__ out) {
    extern __shared__ __align__(128) char smem[];
    const uint32_t sb = smem_to_u32(smem);
    const uint32_t Qs = sb;                                  // 16K
    const uint32_t Kbuf0 = sb + 16384, Kbuf1 = sb + 49152;   // 32K each (256 keys)
    const uint32_t Vbuf0 = sb + 81920, Vbuf1 = sb + 114688;  // 32K each

    const int t = threadIdx.x;
    const int w = t >> 5, lane = t & 31;
    const int gid = lane >> 2, tig = lane & 3;
    const int wr = w >> 1, wc = w & 1;
    const int r0 = wr * 32;
    const int jc = wc * 32;  // key offset within each 64-key sub-tile
    const int bh = blockIdx.y, qb = blockIdx.x;
    const int n0q = qb * 128;
    const __half* qg = g_q16 + (size_t)bh * 4096 * 64;
    const __half* kg = g_k16 + (size_t)bh * 4096 * 64;
    const __half* vg = g_v16 + (size_t)bh * 64 * 4096;

    // stage round r's 256 keys: 4096 x 16B chunks, 256 threads
    auto stage_round = [&](int r, uint32_t Kb, uint32_t Vb) {
        const int base = r * 256;
#pragma unroll
        for (int pass = 0; pass < 16; pass++) {
            int idx = pass * 256 + t;
            if (idx < 2048) {
                int row = idx >> 3, kc = idx & 7;  // row = key 0..255
                cp16(Kb + row * 128 + ((kc * 16) ^ ((row & 7) * 16)),
                     kg + ((size_t)(base + row)) * 64 + kc * 8);
            } else {
                int vidx = idx - 2048;
                int sub = vidx >> 9;             // 0..3
                int dv = (vidx >> 3) & 63;
                int kc = vidx & 7;
                cp16(Vb + sub * 8192 + dv * 128 + ((kc * 16) ^ ((dv & 7) * 16)),
                     vg + (size_t)dv * 4096 + base + sub * 64 + kc * 8);
            }
        }
        CP_COMMIT();
    };

    for (int c = t; c < 1024; c += 256) {
        int row = c >> 3, kc = c & 7;
        cp16(Qs + row * 128 + ((kc * 16) ^ ((row & 7) * 16)),
             qg + (size_t)(n0q + row) * 64 + kc * 8);
    }
    stage_round(0, Kbuf0, Vbuf0);
    cp_wait<0>();
    __syncthreads();

    uint32_t qf[2][4][4];
    {
        const uint32_t qx = (lane & 7) * 16;
#pragma unroll
        for (int mt = 0; mt < 2; mt++) {
            const int qrow = r0 + mt * 16 + ((lane >> 3) & 1) * 8 + (lane & 7);
            const uint32_t qbase = Qs + qrow * 128;
#pragma unroll
            for (int kt = 0; kt < 4; kt++)
                ldm_x4(qf[mt][kt][0], qf[mt][kt][1], qf[mt][kt][2], qf[mt][kt][3],
                       qbase + ((uint32_t)((kt * 2 + (lane >> 4)) * 16) ^ qx));
        }
    }

    int i_lo[2], i_hi[2];
#pragma unroll
    for (int mt = 0; mt < 2; mt++) {
        i_lo[mt] = r0 + mt * 16 + gid;
        i_hi[mt] = i_lo[mt] + 8;
    }

    // ---- width-bias gather -> per-thread smem slab [pair p][thread]
    // p = mt*8 + nt*2 + (0:lo pair | 1:hi pair); each thread reads only its own.
    float2* qws = (float2*)(smem + QW_OFF);
    {
        const float* qwb = g_qw + ((size_t)bh * 4096 + n0q) * 128;
#pragma unroll
        for (int mt = 0; mt < 2; mt++)
#pragma unroll
            for (int nt = 0; nt < 4; nt++) {
                int c = jc + nt * 8 + 2 * tig;
                qws[(mt * 8 + nt * 2 + 0) * 256 + t] = make_float2(
                    qwb[(size_t)i_lo[mt] * 128 + (c - (i_lo[mt] & 63) + 63)],
                    qwb[(size_t)i_lo[mt] * 128 + (c + 1 - (i_lo[mt] & 63) + 63)]);
                qws[(mt * 8 + nt * 2 + 1) * 256 + t] = make_float2(
                    qwb[(size_t)i_hi[mt] * 128 + (c - (i_hi[mt] & 63) + 63)],
                    qwb[(size_t)i_hi[mt] * 128 + (c + 1 - (i_hi[mt] & 63) + 63)]);
            }
    }

    const float* pqh_lo0 =
        g_qh + ((size_t)bh * 4096 + n0q + i_lo[0]) * 128 + 63 - (qb * 2 + (i_lo[0] >> 6));
    const float* pqh_hi0 =
        g_qh + ((size_t)bh * 4096 + n0q + i_hi[0]) * 128 + 63 - (qb * 2 + (i_hi[0] >> 6));
    const float* pqh_lo1 =
        g_qh + ((size_t)bh * 4096 + n0q + i_lo[1]) * 128 + 63 - (qb * 2 + (i_lo[1] >> 6));
    const float* pqh_hi1 =
        g_qh + ((size_t)bh * 4096 + n0q + i_hi[1]) * 128 + 63 - (qb * 2 + (i_hi[1] >> 6));

    const int kv_row = ((lane >> 4) & 1) * 8 + (lane & 7);
    const int kv_csel = (lane >> 3) & 1;
    const uint32_t kv_x = (lane & 7) * 16;

    float l_lo0 = 0.f, l_hi0 = 0.f, l_lo1 = 0.f, l_hi1 = 0.f;
    float O[2][4][4];
    float O2[2][4][4];
#pragma unroll
    for (int mt = 0; mt < 2; mt++)
#pragma unroll
        for (int nt = 0; nt < 4; nt++)
#pragma unroll
            for (int e = 0; e < 4; e++) { O[mt][nt][e] = 0.f; O2[mt][nt][e] = 0.f; }

    // ---- S computation: 2 m-tiles x this warp's 32 keys of sub-tile at Kbs
    auto compute_S = [&](float (&S)[2][4][4], uint32_t Kbs) {
#pragma unroll
        for (int mt = 0; mt < 2; mt++)
#pragma unroll
            for (int nt = 0; nt < 4; nt++)
#pragma unroll
                for (int e = 0; e < 4; e++) S[mt][nt][e] = 0.f;
#pragma unroll
        for (int kt = 0; kt < 4; kt++) {
#pragma unroll
            for (int ntl = 0; ntl < 2; ntl++) {
                uint32_t b0, b1, b2, b3;
                uint32_t addr = Kbs + (uint32_t)(jc + ntl * 16 + kv_row) * 128 +
                                ((uint32_t)((kt * 2 + kv_csel) * 16) ^ kv_x);
                ldm_x4(b0, b1, b2, b3, addr);
#pragma unroll
                for (int mt = 0; mt < 2; mt++) {
                    mma_f16(S[mt][2 * ntl], qf[mt][kt][0], qf[mt][kt][1],
                            qf[mt][kt][2], qf[mt][kt][3], b0, b1);
                    mma_f16(S[mt][2 * ntl + 1], qf[mt][kt][0], qf[mt][kt][1],
                            qf[mt][kt][2], qf[mt][kt][3], b2, b3);
                }
            }
        }
    };

    // ---- exp + O accumulate for sub-tile j with S in hand, V at Vbs
    auto exp_O = [&](float (&S)[2][4][4], int j, uint32_t Vbs) {
        const float qhc_lo0 = pqh_lo0[j] - EXP_C;
        const float qhc_hi0 = pqh_hi0[j] - EXP_C;
        const float qhc_lo1 = pqh_lo1[j] - EXP_C;
        const float qhc_hi1 = pqh_hi1[j] - EXP_C;

        uint32_t ph[2][4][2];
        uint32_t hl0 = 0, hh0 = 0, hl1 = 0, hh1 = 0;
#pragma unroll
        for (int nt = 0; nt < 4; nt++) {
            {
                const float2 blo = qws[(0 * 8 + nt * 2 + 0) * 256 + t];
                const float2 bhi = qws[(0 * 8 + nt * 2 + 1) * 256 + t];
                uint32_t p0 = h2ex2(packh2(S[0][nt][0] + (qhc_lo0 + blo.x),
                                           S[0][nt][1] + (qhc_lo0 + blo.y)));
                uint32_t p1 = h2ex2(packh2(S[0][nt][2] + (qhc_hi0 + bhi.x),
                                           S[0][nt][3] + (qhc_hi0 + bhi.y)));
                ph[0][nt][0] = p0;
                ph[0][nt][1] = p1;
                hl0 = hadd2u(hl0, p0);
                hh0 = hadd2u(hh0, p1);
            }
            {
                const float2 blo = qws[(1 * 8 + nt * 2 + 0) * 256 + t];
                const float2 bhi = qws[(1 * 8 + nt * 2 + 1) * 256 + t];
                uint32_t p0 = h2ex2(packh2(S[1][nt][0] + (qhc_lo1 + blo.x),
                                           S[1][nt][1] + (qhc_lo1 + blo.y)));
                uint32_t p1 = h2ex2(packh2(S[1][nt][2] + (qhc_hi1 + bhi.x),
                                           S[1][nt][3] + (qhc_hi1 + bhi.y)));
                ph[1][nt][0] = p0;
                ph[1][nt][1] = p1;
                hl1 = hadd2u(hl1, p0);
                hh1 = hadd2u(hh1, p1);
            }
        }
        {
            float2 f;
            f = __half22float2(*(__half2*)&hl0); l_lo0 += f.x + f.y;
            f = __half22float2(*(__half2*)&hh0); l_hi0 += f.x + f.y;
            f = __half22float2(*(__half2*)&hl1); l_lo1 += f.x + f.y;
            f = __half22float2(*(__half2*)&hh1); l_hi1 += f.x + f.y;
        }

#pragma unroll
        for (int ktl = 0; ktl < 2; ktl++) {
#pragma unroll
            for (int ntp = 0; ntp < 4; ntp++) {
                uint32_t b0, b1, b2, b3;
                uint32_t addr = Vbs + (uint32_t)(ntp * 16 + kv_row) * 128 +
                                ((uint32_t)((wc * 4 + ktl * 2 + kv_csel) * 16) ^ kv_x);
                ldm_x4(b0, b1, b2, b3, addr);
#pragma unroll
                for (int mt = 0; mt < 2; mt++) {
                    const uint32_t pa0 = ph[mt][2 * ktl][0], pa1 = ph[mt][2 * ktl][1];
                    const uint32_t pa2 = ph[mt][2 * ktl + 1][0], pa3 = ph[mt][2 * ktl + 1][1];
                    float* d0 = (ntp < 2) ? O[mt][2 * ntp] : O2[mt][2 * (ntp - 2)];
                    float* d1 = (ntp < 2) ? O[mt][2 * ntp + 1] : O2[mt][2 * (ntp - 2) + 1];
                    mma_f16(d0, pa0, pa1, pa2, pa3, b0, b1);
                    mma_f16(d1, pa0, pa1, pa2, pa3, b2, b3);
                }
            }
        }
    };

    float Sa[2][4][4], Sb[2][4][4];

    for (int r = 0; r < 16; r++) {
        __syncthreads();
        if (r + 1 < 16) {
            stage_round(r + 1, (r & 1) ? Kbuf0 : Kbuf1, (r & 1) ? Vbuf0 : Vbuf1);
            cp_wait<1>();
        } else {
            cp_wait<0>();
        }
        __syncthreads();

        const uint32_t Kb = (r & 1) ? Kbuf1 : Kbuf0;
        const uint32_t Vb = (r & 1) ? Vbuf1 : Vbuf0;
        const int j0 = 4 * r;

        // software pipeline: S(sub+1) issued before exp/O(sub)
        compute_S(Sa, Kb);
        compute_S(Sb, Kb + 8192);
        exp_O(Sa, j0 + 0, Vb);
        compute_S(Sa, Kb + 16384);
        exp_O(Sb, j0 + 1, Vb + 8192);
        compute_S(Sb, Kb + 24576);
        exp_O(Sa, j0 + 2, Vb + 16384);
        exp_O(Sb, j0 + 3, Vb + 24576);
    }

    // ---- quad reduction of l
    l_lo0 += __shfl_xor_sync(0xffffffffu, l_lo0, 1);
    l_lo0 += __shfl_xor_sync(0xffffffffu, l_lo0, 2);
    l_hi0 += __shfl_xor_sync(0xffffffffu, l_hi0, 1);
    l_hi0 += __shfl_xor_sync(0xffffffffu, l_hi0, 2);
    l_lo1 += __shfl_xor_sync(0xffffffffu, l_lo1, 1);
    l_lo1 += __shfl_xor_sync(0xffffffffu, l_lo1, 2);
    l_hi1 += __shfl_xor_sync(0xffffffffu, l_hi1, 1);
    l_hi1 += __shfl_xor_sync(0xffffffffu, l_hi1, 2);

    __syncthreads();

    float* Os = (float*)smem;                    // [dv][i] stride 132
    float* lpart = (float*)(smem + 33792);       // [128]
    float* Opart = (float*)(smem + 34816);       // [i][dv] stride 66

    if (wc == 1) {
#pragma unroll
        for (int mt = 0; mt < 2; mt++) {
#pragma unroll
            for (int nt = 0; nt < 4; nt++) {
                int c0 = nt * 8 + 2 * tig;
                int c1 = 32 + nt * 8 + 2 * tig;
                *(float2*)(Opart + i_lo[mt] * 66 + c0) = make_float2(O[mt][nt][0], O[mt][nt][1]);
                *(float2*)(Opart + i_hi[mt] * 66 + c0) = make_float2(O[mt][nt][2], O[mt][nt][3]);
                *(float2*)(Opart + i_lo[mt] * 66 + c1) = make_float2(O2[mt][nt][0], O2[mt][nt][1]);
                *(float2*)(Opart + i_hi[mt] * 66 + c1) = make_float2(O2[mt][nt][2], O2[mt][nt][3]);
            }
        }
        if (tig == 0) {
            lpart[i_lo[0]] = l_lo0; lpart[i_hi[0]] = l_hi0;
            lpart[i_lo[1]] = l_lo1; lpart[i_hi[1]] = l_hi1;
        }
    }
    __syncthreads();
    if (wc == 0) {
        const float inv_lo0 = 1.0f / (l_lo0 + lpart[i_lo[0]]);
        const float inv_hi0 = 1.0f / (l_hi0 + lpart[i_hi[0]]);
        const float inv_lo1 = 1.0f / (l_lo1 + lpart[i_lo[1]]);
        const float inv_hi1 = 1.0f / (l_hi1 + lpart[i_hi[1]]);
#pragma unroll
        for (int mt = 0; mt < 2; mt++) {
            const float inv_lo = mt ? inv_lo1 : inv_lo0;
            const float inv_hi = mt ? inv_hi1 : inv_hi0;
#pragma unroll
            for (int nt = 0; nt < 4; nt++) {
                int c0 = nt * 8 + 2 * tig;
                int c1 = 32 + nt * 8 + 2 * tig;
                float2 p;
                p = *(const float2*)(Opart + i_lo[mt] * 66 + c0);
                Os[(c0 + 0) * 132 + i_lo[mt]] = (O[mt][nt][0] + p.x) * inv_lo;
                Os[(c0 + 1) * 132 + i_lo[mt]] = (O[mt][nt][1] + p.y) * inv_lo;
                p = *(const float2*)(Opart + i_hi[mt] * 66 + c0);
                Os[(c0 + 0) * 132 + i_hi[mt]] = (O[mt][nt][2] + p.x) * inv_hi;
                Os[(c0 + 1) * 132 + i_hi[mt]] = (O[mt][nt][3] + p.y) * inv_hi;
                p = *(const float2*)(Opart + i_lo[mt] * 66 + c1);
                Os[(c1 + 0) * 132 + i_lo[mt]] = (O2[mt][nt][0] + p.x) * inv_lo;
                Os[(c1 + 1) * 132 + i_lo[mt]] = (O2[mt][nt][1] + p.y) * inv_lo;
                p = *(const float2*)(Opart + i_hi[mt] * 66 + c1);
                Os[(c1 + 0) * 132 + i_hi[mt]] = (O2[mt][nt][2] + p.x) * inv_hi;
                Os[(c1 + 1) * 132 + i_hi[mt]] = (O2[mt][nt][3] + p.y) * inv_hi;
            }
        }
    }
    __syncthreads();

    const int b = bh >> 2, head = bh & 3;
    float* outp = out + ((size_t)(b * 256 + head * 64)) * 4096 + n0q;
    for (int idx = t * 4; idx < 8192; idx += 1024) {
        int dv = idx >> 7, i = idx & 127;
        *(float4*)(outp + (size_t)dv * 4096 + i) = *(const float4*)(Os + dv * 132 + i);
    }
}

// ---------------------------------------------------------------------------
extern "C" void kernel_launch(void* const* d_in, const int* in_sizes, int n_in,
                              void* d_out, int out_size) {
    const float* x = (const float*)d_in[0];
    const float* w = (const float*)d_in[1];
    const float* hrel = (const float*)d_in[2];
    const float* wrel = (const float*)d_in[3];
    float* out = (float*)d_out;

    cvt_kernel<<<(X_F4 + W_F4 + 255) / 256, 256>>>(x, w);

    cudaFuncSetAttribute(qkv_mma_kernel, cudaFuncAttributeMaxDynamicSharedMemorySize,
                         65536);
    qkv_mma_kernel<<<dim3(32, 6, 2), 256, 65536>>>();

    rel_mma_kernel<<<dim3(32, 8, 2), 256>>>(hrel, wrel);

    cudaFuncSetAttribute(flash_kernel, cudaFuncAttributeMaxDynamicSharedMemorySize,
                         FL_SMEM);
    flash_kernel<<<dim3(32, 8), 256, FL_SMEM>>>(out);
}